// round 4
// baseline (speedup 1.0000x reference)
#include <cuda_runtime.h>
#include <cuda_bf16.h>
#include <cstdint>

// ---------------------------------------------------------------------------
// Problem dims (fixed by the reference): E=1024, H=16, DQ=DV=64, B=8, S=4096
// ---------------------------------------------------------------------------
#define M_TOK 32768      // B*S tokens
#define K_E   1024       // embedding dim
#define N_QK  2048       // H*(DQ+DQ)

// ---------------------------------------------------------------------------
// Scratch (static __device__ — no runtime allocation allowed)
// ---------------------------------------------------------------------------
__device__ float g_qk[(size_t)M_TOK * N_QK];   // 256 MB
__device__ float g_v [(size_t)M_TOK * K_E];    // 128 MB
__device__ float g_ao[(size_t)M_TOK * K_E];
__device__ float g_p [(size_t)M_TOK * K_E];
__device__ float g_h [(size_t)M_TOK * K_E];
__device__ float g_f [(size_t)M_TOK * K_E];

// ---------------------------------------------------------------------------
// PTX helpers
// ---------------------------------------------------------------------------
__device__ __forceinline__ uint32_t smem_u32(const void* p) {
    return (uint32_t)__cvta_generic_to_shared(p);
}
__device__ __forceinline__ void cp_async16(uint32_t dst, const void* src) {
    asm volatile("cp.async.cg.shared.global [%0], [%1], 16;\n" :: "r"(dst), "l"(src));
}
__device__ __forceinline__ void cp_commit() {
    asm volatile("cp.async.commit_group;\n");
}
template <int N>
__device__ __forceinline__ void cp_wait() {
    asm volatile("cp.async.wait_group %0;\n" :: "n"(N));
}
__device__ __forceinline__ void ldsm_x4(uint32_t* r, uint32_t a) {
    asm volatile("ldmatrix.sync.aligned.m8n8.x4.shared.b16 {%0,%1,%2,%3}, [%4];\n"
                 : "=r"(r[0]), "=r"(r[1]), "=r"(r[2]), "=r"(r[3]) : "r"(a));
}
__device__ __forceinline__ void mma_tf32(float* d, const uint32_t* a, const uint32_t* b) {
    asm volatile("mma.sync.aligned.m16n8k8.row.col.f32.tf32.tf32.f32 "
                 "{%0,%1,%2,%3}, {%4,%5,%6,%7}, {%8,%9}, {%0,%1,%2,%3};\n"
                 : "+f"(d[0]), "+f"(d[1]), "+f"(d[2]), "+f"(d[3])
                 : "r"(a[0]), "r"(a[1]), "r"(a[2]), "r"(a[3]),
                   "r"(b[0]), "r"(b[1]));
}

// ---------------------------------------------------------------------------
// tf32 GEMM: C[M,N] = A[M,K] @ W[N,K]^T + bias[N]  (optionally exact GELU)
// Tiles: BM=128, BN=128, BK=32. 256 threads = 8 warps (2x4), warp tile 64x32.
// 2-stage cp.async pipeline, XOR-swizzled smem, ldmatrix fragment loads.
// Assumes M%128==0, N%128==0, K%32==0 (true for all launches here).
// ---------------------------------------------------------------------------
__device__ __forceinline__ void gemm_load_tiles(
    float* as, float* bs, const float* Ag, const float* Wg, int K, int lr, int lc)
{
#pragma unroll
    for (int i = 0; i < 4; ++i) {
        int row = lr + (i << 5);
        int sw  = ((lc ^ (row & 7)) << 2);
        cp_async16(smem_u32(as + row * 32 + sw), Ag + (size_t)row * K + (lc << 2));
        cp_async16(smem_u32(bs + row * 32 + sw), Wg + (size_t)row * K + (lc << 2));
    }
}

template <bool GELU>
__global__ void __launch_bounds__(256, 1) gemm_tf32(
    const float* __restrict__ A, const float* __restrict__ W,
    const float* __restrict__ bias, float* __restrict__ C,
    int M, int N, int K)
{
    extern __shared__ float smem[];   // 2 stages * (4096 A + 4096 B) floats = 64 KB

    const int tid  = threadIdx.x;
    const int lane = tid & 31;
    const int warp = tid >> 5;
    const int bm = blockIdx.y << 7;
    const int bn = blockIdx.x << 7;
    const int wm = (warp & 1) << 6;    // warp row offset (2 warps x 64)
    const int wn = (warp >> 1) << 5;   // warp col offset (4 warps x 32)

    const int lr = tid >> 3;           // cp.async row base 0..31
    const int lc = tid & 7;            // cp.async 16B-group  0..7
    const int KT = K >> 5;

    // ldmatrix lane decode
    const int a_ro = (((lane >> 3) & 1) << 3) + (lane & 7);
    const int a_co = lane >> 4;                       // 0/1
    const int b_no = (((lane >> 4) & 1) << 3) + (lane & 7);
    const int b_co = (lane >> 3) & 1;                 // 0/1

    float acc[4][4][4];
#pragma unroll
    for (int i = 0; i < 4; ++i)
#pragma unroll
        for (int j = 0; j < 4; ++j) {
            acc[i][j][0] = 0.f; acc[i][j][1] = 0.f;
            acc[i][j][2] = 0.f; acc[i][j][3] = 0.f;
        }

    const float* Abase = A + (size_t)bm * K;
    const float* Wbase = W + (size_t)bn * K;

    gemm_load_tiles(smem, smem + 4096, Abase, Wbase, K, lr, lc);
    cp_commit();

    for (int kt = 0; kt < KT; ++kt) {
        const int s = kt & 1;
        if (kt + 1 < KT) {
            float* as = smem + ((s ^ 1) ? 8192 : 0);
            gemm_load_tiles(as, as + 4096,
                            Abase + ((kt + 1) << 5), Wbase + ((kt + 1) << 5),
                            K, lr, lc);
            cp_commit();
            cp_wait<1>();
        } else {
            cp_wait<0>();
        }
        __syncthreads();

        const float* as = smem + (s ? 8192 : 0);
        const float* bs = as + 4096;

#pragma unroll
        for (int ks = 0; ks < 4; ++ks) {
            const int cgb = ks << 1;
            uint32_t af[4][4];
            uint32_t bf[4][2];
#pragma unroll
            for (int mi = 0; mi < 4; ++mi) {
                int row = wm + (mi << 4) + a_ro;
                int cg  = cgb + a_co;
                ldsm_x4(af[mi], smem_u32(as + row * 32 + ((cg ^ (row & 7)) << 2)));
            }
#pragma unroll
            for (int jj = 0; jj < 2; ++jj) {
                int n  = wn + (jj << 4) + b_no;
                int cg = cgb + b_co;
                uint32_t t[4];
                ldsm_x4(t, smem_u32(bs + n * 32 + ((cg ^ (n & 7)) << 2)));
                bf[jj * 2    ][0] = t[0]; bf[jj * 2    ][1] = t[1];
                bf[jj * 2 + 1][0] = t[2]; bf[jj * 2 + 1][1] = t[3];
            }
#pragma unroll
            for (int mi = 0; mi < 4; ++mi)
#pragma unroll
                for (int nj = 0; nj < 4; ++nj)
                    mma_tf32(acc[mi][nj], af[mi], bf[nj]);
        }
        __syncthreads();
    }

    // epilogue: bias (+gelu) + 8B stores
    const int g  = lane >> 2;
    const int tg = lane & 3;
#pragma unroll
    for (int mi = 0; mi < 4; ++mi) {
        int r0 = bm + wm + (mi << 4) + g;
#pragma unroll
        for (int nj = 0; nj < 4; ++nj) {
            int col = bn + wn + (nj << 3) + (tg << 1);
            float b0 = bias[col], b1 = bias[col + 1];
            float v0 = acc[mi][nj][0] + b0;
            float v1 = acc[mi][nj][1] + b1;
            float v2 = acc[mi][nj][2] + b0;
            float v3 = acc[mi][nj][3] + b1;
            if (GELU) {
                v0 *= normcdff(v0);
                v1 *= normcdff(v1);
                v2 *= normcdff(v2);
                v3 *= normcdff(v3);
            }
            *(float2*)(C + (size_t)r0 * N + col)       = make_float2(v0, v1);
            *(float2*)(C + (size_t)(r0 + 8) * N + col) = make_float2(v2, v3);
        }
    }
}

// ---------------------------------------------------------------------------
// Per-token head attention: 16x16 scores over heads, softmax, attn @ v.
// One CTA (128 threads) per token. Memory-bound.
// qk row: [q(h,d) | k(h,d)] each 1024; v row: v(h,d) 1024.
// ---------------------------------------------------------------------------
__global__ void __launch_bounds__(128) attn_kernel(
    const float* __restrict__ QK, const float* __restrict__ V,
    float* __restrict__ O)
{
    const int t   = blockIdx.x;
    const int tid = threadIdx.x;
    __shared__ float qs[1024], ks2[1024], vs[1024], at[256];

    const float4* qk4 = (const float4*)(QK + (size_t)t * 2048);
    const float4* v4  = (const float4*)(V  + (size_t)t * 1024);
#pragma unroll
    for (int i = tid; i < 256; i += 128) {
        ((float4*)qs )[i] = qk4[i];
        ((float4*)ks2)[i] = qk4[256 + i];
        ((float4*)vs )[i] = v4[i];
    }
    __syncthreads();

    // 256 scores, 2 per thread: s(h,g) = q[h]·k[g] / 8
#pragma unroll
    for (int sidx = tid; sidx < 256; sidx += 128) {
        int h = sidx >> 4, gg = sidx & 15;
        const float4* qp = (const float4*)(qs  + h  * 64);
        const float4* kp = (const float4*)(ks2 + gg * 64);
        float a = 0.f;
#pragma unroll
        for (int d = 0; d < 16; ++d) {
            float4 x = qp[d], y = kp[d];
            a += x.x * y.x + x.y * y.y + x.z * y.z + x.w * y.w;
        }
        at[sidx] = a * 0.125f;
    }
    __syncthreads();

    if (tid < 16) {
        float m = -1e30f;
#pragma unroll
        for (int gg = 0; gg < 16; ++gg) m = fmaxf(m, at[tid * 16 + gg]);
        float s = 0.f;
#pragma unroll
        for (int gg = 0; gg < 16; ++gg) {
            float e = expf(at[tid * 16 + gg] - m);
            at[tid * 16 + gg] = e;
            s += e;
        }
        float inv = 1.f / s;
#pragma unroll
        for (int gg = 0; gg < 16; ++gg) at[tid * 16 + gg] *= inv;
    }
    __syncthreads();

    float* out = O + (size_t)t * 1024;
#pragma unroll
    for (int o = tid; o < 1024; o += 128) {
        int h = o >> 6, d = o & 63;
        float a = 0.f;
#pragma unroll
        for (int gg = 0; gg < 16; ++gg) a += at[h * 16 + gg] * vs[gg * 64 + d];
        out[o] = a;
    }
}

// ---------------------------------------------------------------------------
// LayerNorm of (P + X) over last dim 1024, scale g, shift b.
// One warp per token; row lives in registers (8 x float4 per lane).
// ---------------------------------------------------------------------------
__global__ void __launch_bounds__(256) ln_kernel(
    const float* __restrict__ P, const float* __restrict__ X,
    const float* __restrict__ gw, const float* __restrict__ bw,
    float* __restrict__ O)
{
    const int t    = blockIdx.x * 8 + (threadIdx.x >> 5);
    const int lane = threadIdx.x & 31;
    const float4* p4 = (const float4*)(P + (size_t)t * 1024);
    const float4* x4 = (const float4*)(X + (size_t)t * 1024);

    float4 v[8];
    float s = 0.f;
#pragma unroll
    for (int j = 0; j < 8; ++j) {
        float4 a = p4[lane + (j << 5)];
        float4 c = x4[lane + (j << 5)];
        v[j].x = a.x + c.x; v[j].y = a.y + c.y;
        v[j].z = a.z + c.z; v[j].w = a.w + c.w;
        s += v[j].x + v[j].y + v[j].z + v[j].w;
    }
#pragma unroll
    for (int o = 16; o > 0; o >>= 1) s += __shfl_xor_sync(0xffffffffu, s, o);
    const float mu = s * (1.0f / 1024.0f);

    float q = 0.f;
#pragma unroll
    for (int j = 0; j < 8; ++j) {
        float dx;
        dx = v[j].x - mu; q += dx * dx;
        dx = v[j].y - mu; q += dx * dx;
        dx = v[j].z - mu; q += dx * dx;
        dx = v[j].w - mu; q += dx * dx;
    }
#pragma unroll
    for (int o = 16; o > 0; o >>= 1) q += __shfl_xor_sync(0xffffffffu, q, o);
    const float r = rsqrtf(q * (1.0f / 1024.0f) + 1e-5f);

    const float4* g4 = (const float4*)gw;
    const float4* b4 = (const float4*)bw;
    float4* o4 = (float4*)(O + (size_t)t * 1024);
#pragma unroll
    for (int j = 0; j < 8; ++j) {
        int i = lane + (j << 5);
        float4 gg = g4[i], bb = b4[i], ov;
        ov.x = (v[j].x - mu) * r * gg.x + bb.x;
        ov.y = (v[j].y - mu) * r * gg.y + bb.y;
        ov.z = (v[j].z - mu) * r * gg.z + bb.z;
        ov.w = (v[j].w - mu) * r * gg.w + bb.w;
        o4[i] = ov;
    }
}

// ---------------------------------------------------------------------------
// Launch
// ---------------------------------------------------------------------------
extern "C" void kernel_launch(void* const* d_in, const int* in_sizes, int n_in,
                              void* d_out, int out_size)
{
    const float* x      = (const float*)d_in[0];
    const float* qk_w   = (const float*)d_in[1];
    const float* qk_b   = (const float*)d_in[2];
    const float* v_w    = (const float*)d_in[3];
    const float* v_b    = (const float*)d_in[4];
    const float* proj_w = (const float*)d_in[5];
    const float* proj_b = (const float*)d_in[6];
    const float* ff_w   = (const float*)d_in[7];
    const float* ff_b   = (const float*)d_in[8];
    const float* ln_g   = (const float*)d_in[9];
    const float* ln_b   = (const float*)d_in[10];
    float* out = (float*)d_out;

    (void)in_sizes; (void)n_in; (void)out_size;

    cudaFuncSetAttribute(gemm_tf32<false>,
                         cudaFuncAttributeMaxDynamicSharedMemorySize, 65536);
    cudaFuncSetAttribute(gemm_tf32<true>,
                         cudaFuncAttributeMaxDynamicSharedMemorySize, 65536);

    float *qk, *v, *ao, *p, *h, *f;
    cudaGetSymbolAddress((void**)&qk, g_qk);
    cudaGetSymbolAddress((void**)&v,  g_v);
    cudaGetSymbolAddress((void**)&ao, g_ao);
    cudaGetSymbolAddress((void**)&p,  g_p);
    cudaGetSymbolAddress((void**)&h,  g_h);
    cudaGetSymbolAddress((void**)&f,  g_f);

    const dim3 blk(256);

    // 1-2: QKV projections
    gemm_tf32<false><<<dim3(N_QK / 128, M_TOK / 128), blk, 65536>>>(
        x, qk_w, qk_b, qk, M_TOK, N_QK, K_E);
    gemm_tf32<false><<<dim3(K_E / 128, M_TOK / 128), blk, 65536>>>(
        x, v_w, v_b, v, M_TOK, K_E, K_E);

    // 3: per-token head attention
    attn_kernel<<<M_TOK, 128>>>(qk, v, ao);

    // 4: output projection
    gemm_tf32<false><<<dim3(K_E / 128, M_TOK / 128), blk, 65536>>>(
        ao, proj_w, proj_b, p, M_TOK, K_E, K_E);

    // 5: h = LN(p + x)
    ln_kernel<<<M_TOK / 8, 256>>>(p, x, ln_g, ln_b, h);

    // 6: f = gelu(h @ ff_w^T + ff_b)
    gemm_tf32<true><<<dim3(K_E / 128, M_TOK / 128), blk, 65536>>>(
        h, ff_w, ff_b, f, M_TOK, K_E, K_E);

    // 7: out = LN(f + x)
    ln_kernel<<<M_TOK / 8, 256>>>(f, x, ln_g, ln_b, out);
}

// round 7
// speedup vs baseline: 1.0775x; 1.0775x over previous
#include <cuda_runtime.h>
#include <cuda_bf16.h>
#include <cstdint>

// ---------------------------------------------------------------------------
// Problem dims (fixed by the reference): E=1024, H=16, DQ=DV=64, B=8, S=4096
// ---------------------------------------------------------------------------
#define M_TOK 32768      // B*S tokens
#define K_E   1024       // embedding dim
#define N_QK  2048       // H*(DQ+DQ)

// ---------------------------------------------------------------------------
// Scratch (static __device__ — no runtime allocation allowed)
// ---------------------------------------------------------------------------
__device__ float g_qk[(size_t)M_TOK * N_QK];
__device__ float g_v [(size_t)M_TOK * K_E];
__device__ float g_ao[(size_t)M_TOK * K_E];
__device__ float g_p [(size_t)M_TOK * K_E];
__device__ float g_h [(size_t)M_TOK * K_E];
__device__ float g_f [(size_t)M_TOK * K_E];

// ---------------------------------------------------------------------------
// PTX helpers (sm_80-class only: the harness targets plain sm_103, no 'a'
// features, so tcgen05/TMA are unavailable — mma.sync tf32 is the ceiling)
// ---------------------------------------------------------------------------
__device__ __forceinline__ uint32_t smem_u32(const void* p) {
    return (uint32_t)__cvta_generic_to_shared(p);
}
__device__ __forceinline__ void cp_async16(uint32_t dst, const void* src) {
    asm volatile("cp.async.cg.shared.global [%0], [%1], 16;\n" :: "r"(dst), "l"(src));
}
__device__ __forceinline__ void cp_commit() {
    asm volatile("cp.async.commit_group;\n");
}
template <int N>
__device__ __forceinline__ void cp_wait() {
    asm volatile("cp.async.wait_group %0;\n" :: "n"(N));
}
__device__ __forceinline__ void ldsm_x4(uint32_t* r, uint32_t a) {
    asm volatile("ldmatrix.sync.aligned.m8n8.x4.shared.b16 {%0,%1,%2,%3}, [%4];\n"
                 : "=r"(r[0]), "=r"(r[1]), "=r"(r[2]), "=r"(r[3]) : "r"(a));
}
__device__ __forceinline__ void mma_tf32(float* d, const uint32_t* a, const uint32_t* b) {
    asm volatile("mma.sync.aligned.m16n8k8.row.col.f32.tf32.tf32.f32 "
                 "{%0,%1,%2,%3}, {%4,%5,%6,%7}, {%8,%9}, {%0,%1,%2,%3};\n"
                 : "+f"(d[0]), "+f"(d[1]), "+f"(d[2]), "+f"(d[3])
                 : "r"(a[0]), "r"(a[1]), "r"(a[2]), "r"(a[3]),
                   "r"(b[0]), "r"(b[1]));
}

// ---------------------------------------------------------------------------
// tf32 GEMM: C[M,N] = A[M,K] @ W[N,K]^T + bias[N]  (optionally exact GELU)
// Tiles: BM=128, BN=128, BK=32. 256 threads = 8 warps (2x4), warp tile 64x32.
// 4-stage cp.async pipeline (128 KB smem), ONE __syncthreads per k-tile,
// register-fragment double buffering with cross-tile ks=0 preload.
// Assumes M%128==0, N%128==0, K%32==0 (true for all launches here).
// ---------------------------------------------------------------------------
#define STAGE_F 8192   // floats per stage: 4096 A + 4096 B
#define GSMEM   (4 * STAGE_F * 4)   // 131072 bytes

__device__ __forceinline__ void gemm_load_tiles(
    float* as, const float* Ag, const float* Wg, int K, int lr, int lc)
{
    float* bs = as + 4096;
#pragma unroll
    for (int i = 0; i < 4; ++i) {
        int row = lr + (i << 5);
        int sw  = ((lc ^ (row & 7)) << 2);
        cp_async16(smem_u32(as + row * 32 + sw), Ag + (size_t)row * K + (lc << 2));
        cp_async16(smem_u32(bs + row * 32 + sw), Wg + (size_t)row * K + (lc << 2));
    }
}

__device__ __forceinline__ void load_frags(
    uint32_t af[4][4], uint32_t bf[4][2], const float* as, int ks,
    int wm, int wn, int a_ro, int a_co, int b_no, int b_co)
{
    const float* bs = as + 4096;
    const int cgb = ks << 1;
#pragma unroll
    for (int mi = 0; mi < 4; ++mi) {
        int row = wm + (mi << 4) + a_ro;
        int cg  = cgb + a_co;
        ldsm_x4(af[mi], smem_u32(as + row * 32 + ((cg ^ (row & 7)) << 2)));
    }
#pragma unroll
    for (int jj = 0; jj < 2; ++jj) {
        int n  = wn + (jj << 4) + b_no;
        int cg = cgb + b_co;
        uint32_t t[4];
        ldsm_x4(t, smem_u32(bs + n * 32 + ((cg ^ (n & 7)) << 2)));
        bf[jj * 2    ][0] = t[0]; bf[jj * 2    ][1] = t[1];
        bf[jj * 2 + 1][0] = t[2]; bf[jj * 2 + 1][1] = t[3];
    }
}

__device__ __forceinline__ void mma_all(
    float acc[4][4][4], uint32_t af[4][4], uint32_t bf[4][2])
{
#pragma unroll
    for (int mi = 0; mi < 4; ++mi)
#pragma unroll
        for (int nj = 0; nj < 4; ++nj)
            mma_tf32(acc[mi][nj], af[mi], bf[nj]);
}

template <bool GELU>
__global__ void __launch_bounds__(256, 1) gemm_tf32(
    const float* __restrict__ A, const float* __restrict__ W,
    const float* __restrict__ bias, float* __restrict__ C,
    int M, int N, int K)
{
    extern __shared__ float smem[];   // 4 stages x 8192 floats = 128 KB

    const int tid  = threadIdx.x;
    const int lane = tid & 31;
    const int warp = tid >> 5;
    const int bm = blockIdx.y << 7;
    const int bn = blockIdx.x << 7;
    const int wm = (warp & 1) << 6;
    const int wn = (warp >> 1) << 5;

    const int lr = tid >> 3;           // cp.async row base 0..31
    const int lc = tid & 7;            // cp.async 16B-group  0..7
    const int KT = K >> 5;

    // ldmatrix lane decode
    const int a_ro = (((lane >> 3) & 1) << 3) + (lane & 7);
    const int a_co = lane >> 4;
    const int b_no = (((lane >> 4) & 1) << 3) + (lane & 7);
    const int b_co = (lane >> 3) & 1;

    float acc[4][4][4];
#pragma unroll
    for (int i = 0; i < 4; ++i)
#pragma unroll
        for (int j = 0; j < 4; ++j) {
            acc[i][j][0] = 0.f; acc[i][j][1] = 0.f;
            acc[i][j][2] = 0.f; acc[i][j][3] = 0.f;
        }

    const float* Abase = A + (size_t)bm * K;
    const float* Wbase = W + (size_t)bn * K;

    // Prologue: fill stages 0..2
#pragma unroll
    for (int p = 0; p < 3; ++p) {
        gemm_load_tiles(smem + p * STAGE_F, Abase + (p << 5), Wbase + (p << 5),
                        K, lr, lc);
        cp_commit();
    }
    cp_wait<2>();            // stage 0 resident
    __syncthreads();

    uint32_t af[2][4][4], bf[2][4][2];
    load_frags(af[0], bf[0], smem, 0, wm, wn, a_ro, a_co, b_no, b_co);
    int cur = 0;

    for (int kt = 0; kt < KT; ++kt) {
        const float* as = smem + (kt & 3) * STAGE_F;

#pragma unroll
        for (int ks = 0; ks < 3; ++ks) {
            load_frags(af[cur ^ 1], bf[cur ^ 1], as, ks + 1,
                       wm, wn, a_ro, a_co, b_no, b_co);
            mma_all(acc, af[cur], bf[cur]);
            cur ^= 1;
        }

        if (kt + 1 < KT) {
            // retire oldest in-flight tile, then refill the stage freed at kt-1
            cp_wait<1>();
            __syncthreads();
            if (kt + 3 < KT)
                gemm_load_tiles(smem + ((kt + 3) & 3) * STAGE_F,
                                Abase + ((kt + 3) << 5), Wbase + ((kt + 3) << 5),
                                K, lr, lc);
            cp_commit();
            // preload next tile's ks=0 fragments; ks=3 MMA below overlaps it
            load_frags(af[cur ^ 1], bf[cur ^ 1],
                       smem + ((kt + 1) & 3) * STAGE_F, 0,
                       wm, wn, a_ro, a_co, b_no, b_co);
        }
        mma_all(acc, af[cur], bf[cur]);    // ks = 3
        cur ^= 1;
    }

    // epilogue: bias (+gelu) + 8B stores
    const int g  = lane >> 2;
    const int tg = lane & 3;
#pragma unroll
    for (int mi = 0; mi < 4; ++mi) {
        int r0 = bm + wm + (mi << 4) + g;
#pragma unroll
        for (int nj = 0; nj < 4; ++nj) {
            int col = bn + wn + (nj << 3) + (tg << 1);
            float b0 = bias[col], b1 = bias[col + 1];
            float v0 = acc[mi][nj][0] + b0;
            float v1 = acc[mi][nj][1] + b1;
            float v2 = acc[mi][nj][2] + b0;
            float v3 = acc[mi][nj][3] + b1;
            if (GELU) {
                v0 *= normcdff(v0);
                v1 *= normcdff(v1);
                v2 *= normcdff(v2);
                v3 *= normcdff(v3);
            }
            *(float2*)(C + (size_t)r0 * N + col)       = make_float2(v0, v1);
            *(float2*)(C + (size_t)(r0 + 8) * N + col) = make_float2(v2, v3);
        }
    }
}

// ---------------------------------------------------------------------------
// Per-token head attention: 16x16 scores over heads, softmax, attn @ v.
// One CTA (128 threads) per token. Memory-bound.
// ---------------------------------------------------------------------------
__global__ void __launch_bounds__(128) attn_kernel(
    const float* __restrict__ QK, const float* __restrict__ V,
    float* __restrict__ O)
{
    const int t   = blockIdx.x;
    const int tid = threadIdx.x;
    __shared__ float qs[1024], ks2[1024], vs[1024], at[256];

    const float4* qk4 = (const float4*)(QK + (size_t)t * 2048);
    const float4* v4  = (const float4*)(V  + (size_t)t * 1024);
#pragma unroll
    for (int i = tid; i < 256; i += 128) {
        ((float4*)qs )[i] = qk4[i];
        ((float4*)ks2)[i] = qk4[256 + i];
        ((float4*)vs )[i] = v4[i];
    }
    __syncthreads();

#pragma unroll
    for (int sidx = tid; sidx < 256; sidx += 128) {
        int h = sidx >> 4, gg = sidx & 15;
        const float4* qp = (const float4*)(qs  + h  * 64);
        const float4* kp = (const float4*)(ks2 + gg * 64);
        float a = 0.f;
#pragma unroll
        for (int d = 0; d < 16; ++d) {
            float4 x = qp[d], y = kp[d];
            a += x.x * y.x + x.y * y.y + x.z * y.z + x.w * y.w;
        }
        at[sidx] = a * 0.125f;
    }
    __syncthreads();

    if (tid < 16) {
        float m = -1e30f;
#pragma unroll
        for (int gg = 0; gg < 16; ++gg) m = fmaxf(m, at[tid * 16 + gg]);
        float s = 0.f;
#pragma unroll
        for (int gg = 0; gg < 16; ++gg) {
            float e = expf(at[tid * 16 + gg] - m);
            at[tid * 16 + gg] = e;
            s += e;
        }
        float inv = 1.f / s;
#pragma unroll
        for (int gg = 0; gg < 16; ++gg) at[tid * 16 + gg] *= inv;
    }
    __syncthreads();

    float* out = O + (size_t)t * 1024;
#pragma unroll
    for (int o = tid; o < 1024; o += 128) {
        int h = o >> 6, d = o & 63;
        float a = 0.f;
#pragma unroll
        for (int gg = 0; gg < 16; ++gg) a += at[h * 16 + gg] * vs[gg * 64 + d];
        out[o] = a;
    }
}

// ---------------------------------------------------------------------------
// LayerNorm of (P + X) over last dim 1024, scale g, shift b.
// One warp per token; row lives in registers.
// ---------------------------------------------------------------------------
__global__ void __launch_bounds__(256) ln_kernel(
    const float* __restrict__ P, const float* __restrict__ X,
    const float* __restrict__ gw, const float* __restrict__ bw,
    float* __restrict__ O)
{
    const int t    = blockIdx.x * 8 + (threadIdx.x >> 5);
    const int lane = threadIdx.x & 31;
    const float4* p4 = (const float4*)(P + (size_t)t * 1024);
    const float4* x4 = (const float4*)(X + (size_t)t * 1024);

    float4 v[8];
    float s = 0.f;
#pragma unroll
    for (int j = 0; j < 8; ++j) {
        float4 a = p4[lane + (j << 5)];
        float4 c = x4[lane + (j << 5)];
        v[j].x = a.x + c.x; v[j].y = a.y + c.y;
        v[j].z = a.z + c.z; v[j].w = a.w + c.w;
        s += v[j].x + v[j].y + v[j].z + v[j].w;
    }
#pragma unroll
    for (int o = 16; o > 0; o >>= 1) s += __shfl_xor_sync(0xffffffffu, s, o);
    const float mu = s * (1.0f / 1024.0f);

    float q = 0.f;
#pragma unroll
    for (int j = 0; j < 8; ++j) {
        float dx;
        dx = v[j].x - mu; q += dx * dx;
        dx = v[j].y - mu; q += dx * dx;
        dx = v[j].z - mu; q += dx * dx;
        dx = v[j].w - mu; q += dx * dx;
    }
#pragma unroll
    for (int o = 16; o > 0; o >>= 1) q += __shfl_xor_sync(0xffffffffu, q, o);
    const float r = rsqrtf(q * (1.0f / 1024.0f) + 1e-5f);

    const float4* g4 = (const float4*)gw;
    const float4* b4 = (const float4*)bw;
    float4* o4 = (float4*)(O + (size_t)t * 1024);
#pragma unroll
    for (int j = 0; j < 8; ++j) {
        int i = lane + (j << 5);
        float4 gg = g4[i], bb = b4[i], ov;
        ov.x = (v[j].x - mu) * r * gg.x + bb.x;
        ov.y = (v[j].y - mu) * r * gg.y + bb.y;
        ov.z = (v[j].z - mu) * r * gg.z + bb.z;
        ov.w = (v[j].w - mu) * r * gg.w + bb.w;
        o4[i] = ov;
    }
}

// ---------------------------------------------------------------------------
// Launch
// ---------------------------------------------------------------------------
extern "C" void kernel_launch(void* const* d_in, const int* in_sizes, int n_in,
                              void* d_out, int out_size)
{
    const float* x      = (const float*)d_in[0];
    const float* qk_w   = (const float*)d_in[1];
    const float* qk_b   = (const float*)d_in[2];
    const float* v_w    = (const float*)d_in[3];
    const float* v_b    = (const float*)d_in[4];
    const float* proj_w = (const float*)d_in[5];
    const float* proj_b = (const float*)d_in[6];
    const float* ff_w   = (const float*)d_in[7];
    const float* ff_b   = (const float*)d_in[8];
    const float* ln_g   = (const float*)d_in[9];
    const float* ln_b   = (const float*)d_in[10];
    float* out = (float*)d_out;
    (void)in_sizes; (void)n_in; (void)out_size;

    cudaFuncSetAttribute(gemm_tf32<false>,
                         cudaFuncAttributeMaxDynamicSharedMemorySize, GSMEM);
    cudaFuncSetAttribute(gemm_tf32<true>,
                         cudaFuncAttributeMaxDynamicSharedMemorySize, GSMEM);

    float *qk, *v, *ao, *p, *h, *f;
    cudaGetSymbolAddress((void**)&qk, g_qk);
    cudaGetSymbolAddress((void**)&v,  g_v);
    cudaGetSymbolAddress((void**)&ao, g_ao);
    cudaGetSymbolAddress((void**)&p,  g_p);
    cudaGetSymbolAddress((void**)&h,  g_h);
    cudaGetSymbolAddress((void**)&f,  g_f);

    const dim3 blk(256);

    // 1-2: QKV projections
    gemm_tf32<false><<<dim3(N_QK / 128, M_TOK / 128), blk, GSMEM>>>(
        x, qk_w, qk_b, qk, M_TOK, N_QK, K_E);
    gemm_tf32<false><<<dim3(K_E / 128, M_TOK / 128), blk, GSMEM>>>(
        x, v_w, v_b, v, M_TOK, K_E, K_E);

    // 3: per-token head attention
    attn_kernel<<<M_TOK, 128>>>(qk, v, ao);

    // 4: output projection
    gemm_tf32<false><<<dim3(K_E / 128, M_TOK / 128), blk, GSMEM>>>(
        ao, proj_w, proj_b, p, M_TOK, K_E, K_E);

    // 5: h = LN(p + x)
    ln_kernel<<<M_TOK / 8, 256>>>(p, x, ln_g, ln_b, h);

    // 6: f = gelu(h @ ff_w^T + ff_b)
    gemm_tf32<true><<<dim3(K_E / 128, M_TOK / 128), blk, GSMEM>>>(
        h, ff_w, ff_b, f, M_TOK, K_E, K_E);

    // 7: out = LN(f + x)
    ln_kernel<<<M_TOK / 8, 256>>>(f, x, ln_g, ln_b, out);
}

// round 8
// speedup vs baseline: 1.1047x; 1.0252x over previous
#include <cuda_runtime.h>
#include <cuda_bf16.h>
#include <cstdint>

// ---------------------------------------------------------------------------
// Problem dims (fixed by the reference): E=1024, H=16, DQ=DV=64, B=8, S=4096
// ---------------------------------------------------------------------------
#define M_TOK 32768      // B*S tokens
#define K_E   1024       // embedding dim
#define N_QK  2048       // H*(DQ+DQ)

// ---------------------------------------------------------------------------
// Scratch (static __device__ — no runtime allocation allowed)
// ---------------------------------------------------------------------------
__device__ float g_qk[(size_t)M_TOK * N_QK];
__device__ float g_v [(size_t)M_TOK * K_E];
__device__ float g_ao[(size_t)M_TOK * K_E];
__device__ float g_p [(size_t)M_TOK * K_E];
__device__ float g_h [(size_t)M_TOK * K_E];
__device__ float g_f [(size_t)M_TOK * K_E];

// ---------------------------------------------------------------------------
// PTX helpers (plain sm_103 target: no 'a'-features, mma.sync tf32 path)
// ---------------------------------------------------------------------------
__device__ __forceinline__ uint32_t smem_u32(const void* p) {
    return (uint32_t)__cvta_generic_to_shared(p);
}
__device__ __forceinline__ void cp_async16(uint32_t dst, const void* src) {
    asm volatile("cp.async.cg.shared.global [%0], [%1], 16;\n" :: "r"(dst), "l"(src));
}
__device__ __forceinline__ void cp_commit() {
    asm volatile("cp.async.commit_group;\n");
}
template <int N>
__device__ __forceinline__ void cp_wait() {
    asm volatile("cp.async.wait_group %0;\n" :: "n"(N));
}
__device__ __forceinline__ void ldsm_x4(uint32_t* r, uint32_t a) {
    asm volatile("ldmatrix.sync.aligned.m8n8.x4.shared.b16 {%0,%1,%2,%3}, [%4];\n"
                 : "=r"(r[0]), "=r"(r[1]), "=r"(r[2]), "=r"(r[3]) : "r"(a));
}
__device__ __forceinline__ void mma_tf32(float* d, const uint32_t* a, const uint32_t* b) {
    asm volatile("mma.sync.aligned.m16n8k8.row.col.f32.tf32.tf32.f32 "
                 "{%0,%1,%2,%3}, {%4,%5,%6,%7}, {%8,%9}, {%0,%1,%2,%3};\n"
                 : "+f"(d[0]), "+f"(d[1]), "+f"(d[2]), "+f"(d[3])
                 : "r"(a[0]), "r"(a[1]), "r"(a[2]), "r"(a[3]),
                   "r"(b[0]), "r"(b[1]));
}

// ---------------------------------------------------------------------------
// tf32 GEMM: C[M,N] = A[M,K] @ W[N,K]^T + bias[N]  (optionally exact GELU)
// Tiles: BM=128, BN=256, BK=32. 256 threads = 8 warps (2x4), warp tile 64x64.
// 4-stage cp.async pipeline (192 KB smem), ONE __syncthreads per k-tile,
// register-fragment double buffering with cross-tile ks=0 preload.
// MMA:LDSM.x4 ratio = 32:8 per warp-ks (vs 16:6 before) — smem BW no longer
// co-binding with the tensor pipe.
// ---------------------------------------------------------------------------
#define STAGE_F 12288   // floats per stage: 4096 A + 8192 B
#define GSMEM   (4 * STAGE_F * 4)   // 196608 bytes

__device__ __forceinline__ void gemm_load_tiles(
    float* as, const float* Ag, const float* Wg, int K, int lr, int lc)
{
    float* bs = as + 4096;
#pragma unroll
    for (int i = 0; i < 4; ++i) {            // A: 128 rows
        int row = lr + (i << 5);
        int sw  = ((lc ^ (row & 7)) << 2);
        cp_async16(smem_u32(as + row * 32 + sw), Ag + (size_t)row * K + (lc << 2));
    }
#pragma unroll
    for (int i = 0; i < 8; ++i) {            // B: 256 rows
        int row = lr + (i << 5);
        int sw  = ((lc ^ (row & 7)) << 2);
        cp_async16(smem_u32(bs + row * 32 + sw), Wg + (size_t)row * K + (lc << 2));
    }
}

__device__ __forceinline__ void load_frags(
    uint32_t af[4][4], uint32_t bf[8][2], const float* as, int ks,
    int wm, int wn, int a_ro, int a_co, int b_no, int b_co)
{
    const float* bs = as + 4096;
    const int cgb = ks << 1;
#pragma unroll
    for (int mi = 0; mi < 4; ++mi) {
        int row = wm + (mi << 4) + a_ro;
        int cg  = cgb + a_co;
        ldsm_x4(af[mi], smem_u32(as + row * 32 + ((cg ^ (row & 7)) << 2)));
    }
#pragma unroll
    for (int jj = 0; jj < 4; ++jj) {
        int n  = wn + (jj << 4) + b_no;
        int cg = cgb + b_co;
        uint32_t t[4];
        ldsm_x4(t, smem_u32(bs + n * 32 + ((cg ^ (n & 7)) << 2)));
        bf[jj * 2    ][0] = t[0]; bf[jj * 2    ][1] = t[1];
        bf[jj * 2 + 1][0] = t[2]; bf[jj * 2 + 1][1] = t[3];
    }
}

__device__ __forceinline__ void mma_all(
    float acc[4][8][4], uint32_t af[4][4], uint32_t bf[8][2])
{
#pragma unroll
    for (int mi = 0; mi < 4; ++mi)
#pragma unroll
        for (int nj = 0; nj < 8; ++nj)
            mma_tf32(acc[mi][nj], af[mi], bf[nj]);
}

template <bool GELU>
__global__ void __launch_bounds__(256, 1) gemm_tf32(
    const float* __restrict__ A, const float* __restrict__ W,
    const float* __restrict__ bias, float* __restrict__ C,
    int M, int N, int K)
{
    extern __shared__ float smem[];   // 4 stages x 12288 floats = 192 KB

    const int tid  = threadIdx.x;
    const int lane = tid & 31;
    const int warp = tid >> 5;
    const int bm = blockIdx.y << 7;
    const int bn = blockIdx.x << 8;
    const int wm = (warp & 1) << 6;    // 2 warps over M (2 x 64)
    const int wn = (warp >> 1) << 6;   // 4 warps over N (4 x 64)

    const int lr = tid >> 3;           // cp.async row base 0..31
    const int lc = tid & 7;            // cp.async 16B-group  0..7
    const int KT = K >> 5;

    // ldmatrix lane decode
    const int a_ro = (((lane >> 3) & 1) << 3) + (lane & 7);
    const int a_co = lane >> 4;
    const int b_no = (((lane >> 4) & 1) << 3) + (lane & 7);
    const int b_co = (lane >> 3) & 1;

    float acc[4][8][4];
#pragma unroll
    for (int i = 0; i < 4; ++i)
#pragma unroll
        for (int j = 0; j < 8; ++j) {
            acc[i][j][0] = 0.f; acc[i][j][1] = 0.f;
            acc[i][j][2] = 0.f; acc[i][j][3] = 0.f;
        }

    const float* Abase = A + (size_t)bm * K;
    const float* Wbase = W + (size_t)bn * K;

    // Prologue: fill stages 0..2
#pragma unroll
    for (int p = 0; p < 3; ++p) {
        gemm_load_tiles(smem + p * STAGE_F, Abase + (p << 5), Wbase + (p << 5),
                        K, lr, lc);
        cp_commit();
    }
    cp_wait<2>();            // stage 0 resident
    __syncthreads();

    uint32_t af[2][4][4], bf[2][8][2];
    load_frags(af[0], bf[0], smem, 0, wm, wn, a_ro, a_co, b_no, b_co);
    int cur = 0;

    for (int kt = 0; kt < KT; ++kt) {
        const float* as = smem + (kt & 3) * STAGE_F;

#pragma unroll
        for (int ks = 0; ks < 3; ++ks) {
            load_frags(af[cur ^ 1], bf[cur ^ 1], as, ks + 1,
                       wm, wn, a_ro, a_co, b_no, b_co);
            mma_all(acc, af[cur], bf[cur]);
            cur ^= 1;
        }

        if (kt + 1 < KT) {
            cp_wait<1>();
            __syncthreads();
            if (kt + 3 < KT)
                gemm_load_tiles(smem + ((kt + 3) & 3) * STAGE_F,
                                Abase + ((kt + 3) << 5), Wbase + ((kt + 3) << 5),
                                K, lr, lc);
            cp_commit();
            // preload next tile's ks=0 fragments; ks=3 MMA below overlaps it
            load_frags(af[cur ^ 1], bf[cur ^ 1],
                       smem + ((kt + 1) & 3) * STAGE_F, 0,
                       wm, wn, a_ro, a_co, b_no, b_co);
        }
        mma_all(acc, af[cur], bf[cur]);    // ks = 3
        cur ^= 1;
    }

    // epilogue: bias (+gelu) + 8B stores
    const int g  = lane >> 2;
    const int tg = lane & 3;
#pragma unroll
    for (int mi = 0; mi < 4; ++mi) {
        int r0 = bm + wm + (mi << 4) + g;
#pragma unroll
        for (int nj = 0; nj < 8; ++nj) {
            int col = bn + wn + (nj << 3) + (tg << 1);
            float b0 = bias[col], b1 = bias[col + 1];
            float v0 = acc[mi][nj][0] + b0;
            float v1 = acc[mi][nj][1] + b1;
            float v2 = acc[mi][nj][2] + b0;
            float v3 = acc[mi][nj][3] + b1;
            if (GELU) {
                v0 *= normcdff(v0);
                v1 *= normcdff(v1);
                v2 *= normcdff(v2);
                v3 *= normcdff(v3);
            }
            *(float2*)(C + (size_t)r0 * N + col)       = make_float2(v0, v1);
            *(float2*)(C + (size_t)(r0 + 8) * N + col) = make_float2(v2, v3);
        }
    }
}

// ---------------------------------------------------------------------------
// Per-token head attention: 16x16 scores over heads, softmax, attn @ v.
// One CTA (128 threads) per token. Memory-bound.
// ---------------------------------------------------------------------------
__global__ void __launch_bounds__(128) attn_kernel(
    const float* __restrict__ QK, const float* __restrict__ V,
    float* __restrict__ O)
{
    const int t   = blockIdx.x;
    const int tid = threadIdx.x;
    __shared__ float qs[1024], ks2[1024], vs[1024], at[256];

    const float4* qk4 = (const float4*)(QK + (size_t)t * 2048);
    const float4* v4  = (const float4*)(V  + (size_t)t * 1024);
#pragma unroll
    for (int i = tid; i < 256; i += 128) {
        ((float4*)qs )[i] = qk4[i];
        ((float4*)ks2)[i] = qk4[256 + i];
        ((float4*)vs )[i] = v4[i];
    }
    __syncthreads();

#pragma unroll
    for (int sidx = tid; sidx < 256; sidx += 128) {
        int h = sidx >> 4, gg = sidx & 15;
        const float4* qp = (const float4*)(qs  + h  * 64);
        const float4* kp = (const float4*)(ks2 + gg * 64);
        float a = 0.f;
#pragma unroll
        for (int d = 0; d < 16; ++d) {
            float4 x = qp[d], y = kp[d];
            a += x.x * y.x + x.y * y.y + x.z * y.z + x.w * y.w;
        }
        at[sidx] = a * 0.125f;
    }
    __syncthreads();

    if (tid < 16) {
        float m = -1e30f;
#pragma unroll
        for (int gg = 0; gg < 16; ++gg) m = fmaxf(m, at[tid * 16 + gg]);
        float s = 0.f;
#pragma unroll
        for (int gg = 0; gg < 16; ++gg) {
            float e = expf(at[tid * 16 + gg] - m);
            at[tid * 16 + gg] = e;
            s += e;
        }
        float inv = 1.f / s;
#pragma unroll
        for (int gg = 0; gg < 16; ++gg) at[tid * 16 + gg] *= inv;
    }
    __syncthreads();

    float* out = O + (size_t)t * 1024;
#pragma unroll
    for (int o = tid; o < 1024; o += 128) {
        int h = o >> 6, d = o & 63;
        float a = 0.f;
#pragma unroll
        for (int gg = 0; gg < 16; ++gg) a += at[h * 16 + gg] * vs[gg * 64 + d];
        out[o] = a;
    }
}

// ---------------------------------------------------------------------------
// LayerNorm of (P + X) over last dim 1024, scale g, shift b.
// One warp per token; row lives in registers.
// ---------------------------------------------------------------------------
__global__ void __launch_bounds__(256) ln_kernel(
    const float* __restrict__ P, const float* __restrict__ X,
    const float* __restrict__ gw, const float* __restrict__ bw,
    float* __restrict__ O)
{
    const int t    = blockIdx.x * 8 + (threadIdx.x >> 5);
    const int lane = threadIdx.x & 31;
    const float4* p4 = (const float4*)(P + (size_t)t * 1024);
    const float4* x4 = (const float4*)(X + (size_t)t * 1024);

    float4 v[8];
    float s = 0.f;
#pragma unroll
    for (int j = 0; j < 8; ++j) {
        float4 a = p4[lane + (j << 5)];
        float4 c = x4[lane + (j << 5)];
        v[j].x = a.x + c.x; v[j].y = a.y + c.y;
        v[j].z = a.z + c.z; v[j].w = a.w + c.w;
        s += v[j].x + v[j].y + v[j].z + v[j].w;
    }
#pragma unroll
    for (int o = 16; o > 0; o >>= 1) s += __shfl_xor_sync(0xffffffffu, s, o);
    const float mu = s * (1.0f / 1024.0f);

    float q = 0.f;
#pragma unroll
    for (int j = 0; j < 8; ++j) {
        float dx;
        dx = v[j].x - mu; q += dx * dx;
        dx = v[j].y - mu; q += dx * dx;
        dx = v[j].z - mu; q += dx * dx;
        dx = v[j].w - mu; q += dx * dx;
    }
#pragma unroll
    for (int o = 16; o > 0; o >>= 1) q += __shfl_xor_sync(0xffffffffu, q, o);
    const float r = rsqrtf(q * (1.0f / 1024.0f) + 1e-5f);

    const float4* g4 = (const float4*)gw;
    const float4* b4 = (const float4*)bw;
    float4* o4 = (float4*)(O + (size_t)t * 1024);
#pragma unroll
    for (int j = 0; j < 8; ++j) {
        int i = lane + (j << 5);
        float4 gg = g4[i], bb = b4[i], ov;
        ov.x = (v[j].x - mu) * r * gg.x + bb.x;
        ov.y = (v[j].y - mu) * r * gg.y + bb.y;
        ov.z = (v[j].z - mu) * r * gg.z + bb.z;
        ov.w = (v[j].w - mu) * r * gg.w + bb.w;
        o4[i] = ov;
    }
}

// ---------------------------------------------------------------------------
// Launch
// ---------------------------------------------------------------------------
extern "C" void kernel_launch(void* const* d_in, const int* in_sizes, int n_in,
                              void* d_out, int out_size)
{
    const float* x      = (const float*)d_in[0];
    const float* qk_w   = (const float*)d_in[1];
    const float* qk_b   = (const float*)d_in[2];
    const float* v_w    = (const float*)d_in[3];
    const float* v_b    = (const float*)d_in[4];
    const float* proj_w = (const float*)d_in[5];
    const float* proj_b = (const float*)d_in[6];
    const float* ff_w   = (const float*)d_in[7];
    const float* ff_b   = (const float*)d_in[8];
    const float* ln_g   = (const float*)d_in[9];
    const float* ln_b   = (const float*)d_in[10];
    float* out = (float*)d_out;
    (void)in_sizes; (void)n_in; (void)out_size;

    cudaFuncSetAttribute(gemm_tf32<false>,
                         cudaFuncAttributeMaxDynamicSharedMemorySize, GSMEM);
    cudaFuncSetAttribute(gemm_tf32<true>,
                         cudaFuncAttributeMaxDynamicSharedMemorySize, GSMEM);

    float *qk, *v, *ao, *p, *h, *f;
    cudaGetSymbolAddress((void**)&qk, g_qk);
    cudaGetSymbolAddress((void**)&v,  g_v);
    cudaGetSymbolAddress((void**)&ao, g_ao);
    cudaGetSymbolAddress((void**)&p,  g_p);
    cudaGetSymbolAddress((void**)&h,  g_h);
    cudaGetSymbolAddress((void**)&f,  g_f);

    const dim3 blk(256);

    // 1-2: QKV projections
    gemm_tf32<false><<<dim3(N_QK / 256, M_TOK / 128), blk, GSMEM>>>(
        x, qk_w, qk_b, qk, M_TOK, N_QK, K_E);
    gemm_tf32<false><<<dim3(K_E / 256, M_TOK / 128), blk, GSMEM>>>(
        x, v_w, v_b, v, M_TOK, K_E, K_E);

    // 3: per-token head attention
    attn_kernel<<<M_TOK, 128>>>(qk, v, ao);

    // 4: output projection
    gemm_tf32<false><<<dim3(K_E / 256, M_TOK / 128), blk, GSMEM>>>(
        ao, proj_w, proj_b, p, M_TOK, K_E, K_E);

    // 5: h = LN(p + x)
    ln_kernel<<<M_TOK / 8, 256>>>(p, x, ln_g, ln_b, h);

    // 6: f = gelu(h @ ff_w^T + ff_b)
    gemm_tf32<true><<<dim3(K_E / 256, M_TOK / 128), blk, GSMEM>>>(
        h, ff_w, ff_b, f, M_TOK, K_E, K_E);

    // 7: out = LN(f + x)
    ln_kernel<<<M_TOK / 8, 256>>>(f, x, ln_g, ln_b, out);
}

// round 10
// speedup vs baseline: 1.2013x; 1.0874x over previous
#include <cuda_runtime.h>
#include <cuda_bf16.h>
#include <cstdint>

// ---------------------------------------------------------------------------
// Problem dims (fixed by the reference): E=1024, H=16, DQ=DV=64, B=8, S=4096
// ---------------------------------------------------------------------------
#define M_TOK 32768      // B*S tokens
#define K_E   1024       // embedding dim
#define N_QK  2048       // H*(DQ+DQ)

// ---------------------------------------------------------------------------
// Scratch (static __device__ — no runtime allocation allowed)
// ---------------------------------------------------------------------------
__device__ float g_qk[(size_t)M_TOK * N_QK];
__device__ float g_v [(size_t)M_TOK * K_E];
__device__ float g_ao[(size_t)M_TOK * K_E];
__device__ float g_p [(size_t)M_TOK * K_E];
__device__ float g_h [(size_t)M_TOK * K_E];
__device__ float g_f [(size_t)M_TOK * K_E];

// ---------------------------------------------------------------------------
// PTX helpers (plain sm_103 target: no 'a'-features, mma.sync tf32 path)
// ---------------------------------------------------------------------------
__device__ __forceinline__ uint32_t smem_u32(const void* p) {
    return (uint32_t)__cvta_generic_to_shared(p);
}
__device__ __forceinline__ void cp_async16(uint32_t dst, const void* src) {
    asm volatile("cp.async.cg.shared.global [%0], [%1], 16;\n" :: "r"(dst), "l"(src));
}
__device__ __forceinline__ void cp_commit() {
    asm volatile("cp.async.commit_group;\n");
}
template <int N>
__device__ __forceinline__ void cp_wait() {
    asm volatile("cp.async.wait_group %0;\n" :: "n"(N));
}
__device__ __forceinline__ void ldsm_x4(uint32_t* r, uint32_t a) {
    asm volatile("ldmatrix.sync.aligned.m8n8.x4.shared.b16 {%0,%1,%2,%3}, [%4];\n"
                 : "=r"(r[0]), "=r"(r[1]), "=r"(r[2]), "=r"(r[3]) : "r"(a));
}
__device__ __forceinline__ void mma_tf32(float* d, const uint32_t* a, const uint32_t* b) {
    asm volatile("mma.sync.aligned.m16n8k8.row.col.f32.tf32.tf32.f32 "
                 "{%0,%1,%2,%3}, {%4,%5,%6,%7}, {%8,%9}, {%0,%1,%2,%3};\n"
                 : "+f"(d[0]), "+f"(d[1]), "+f"(d[2]), "+f"(d[3])
                 : "r"(a[0]), "r"(a[1]), "r"(a[2]), "r"(a[3]),
                   "r"(b[0]), "r"(b[1]));
}

// ---------------------------------------------------------------------------
// tf32 GEMM: C[M,N] = A[M,K] @ W[N,K]^T + bias[N]  (optionally exact GELU)
// Tiles: BM=128, BN=128, BK=32. 128 threads = 4 warps (2x2), warp tile 64x64.
// TWO CTAs per SM: each CTA runs a 3-stage cp.async pipeline (96 KB smem),
// one __syncthreads per k-tile; the co-resident CTA's MMA stream fills this
// CTA's barrier/drain windows. Register-fragment double buffering with
// cross-tile ks=0 preload.
// R9 bug fixed: freed-stage index is (s_cur+2)%3 — the old expression mapped
// s_cur==1 to stage 2 (which held tile kt+1) and corrupted the pipeline.
// ---------------------------------------------------------------------------
#define STAGE_F 8192                 // floats per stage: 4096 A + 4096 B
#define GSMEM   (3 * STAGE_F * 4)    // 98304 bytes

__device__ __forceinline__ void gemm_load_tiles(
    float* as, const float* Ag, const float* Wg, int K, int lr, int lc)
{
    float* bs = as + 4096;
#pragma unroll
    for (int i = 0; i < 8; ++i) {            // A: 128 rows, 16 rows/pass
        int row = lr + (i << 4);
        int sw  = ((lc ^ (row & 7)) << 2);
        cp_async16(smem_u32(as + row * 32 + sw), Ag + (size_t)row * K + (lc << 2));
    }
#pragma unroll
    for (int i = 0; i < 8; ++i) {            // B: 128 rows
        int row = lr + (i << 4);
        int sw  = ((lc ^ (row & 7)) << 2);
        cp_async16(smem_u32(bs + row * 32 + sw), Wg + (size_t)row * K + (lc << 2));
    }
}

__device__ __forceinline__ void load_frags(
    uint32_t af[4][4], uint32_t bf[8][2], const float* as, int ks,
    int wm, int wn, int a_ro, int a_co, int b_no, int b_co)
{
    const float* bs = as + 4096;
    const int cgb = ks << 1;
#pragma unroll
    for (int mi = 0; mi < 4; ++mi) {
        int row = wm + (mi << 4) + a_ro;
        int cg  = cgb + a_co;
        ldsm_x4(af[mi], smem_u32(as + row * 32 + ((cg ^ (row & 7)) << 2)));
    }
#pragma unroll
    for (int jj = 0; jj < 4; ++jj) {
        int n  = wn + (jj << 4) + b_no;
        int cg = cgb + b_co;
        uint32_t t[4];
        ldsm_x4(t, smem_u32(bs + n * 32 + ((cg ^ (n & 7)) << 2)));
        bf[jj * 2    ][0] = t[0]; bf[jj * 2    ][1] = t[1];
        bf[jj * 2 + 1][0] = t[2]; bf[jj * 2 + 1][1] = t[3];
    }
}

__device__ __forceinline__ void mma_all(
    float acc[4][8][4], uint32_t af[4][4], uint32_t bf[8][2])
{
#pragma unroll
    for (int mi = 0; mi < 4; ++mi)
#pragma unroll
        for (int nj = 0; nj < 8; ++nj)
            mma_tf32(acc[mi][nj], af[mi], bf[nj]);
}

template <bool GELU>
__global__ void __launch_bounds__(128, 2) gemm_tf32(
    const float* __restrict__ A, const float* __restrict__ W,
    const float* __restrict__ bias, float* __restrict__ C,
    int M, int N, int K)
{
    extern __shared__ float smem[];   // 3 stages x 8192 floats = 96 KB

    const int tid  = threadIdx.x;
    const int lane = tid & 31;
    const int warp = tid >> 5;
    const int bm = blockIdx.y << 7;
    const int bn = blockIdx.x << 7;
    const int wm = (warp & 1) << 6;    // 2 warps over M (2 x 64)
    const int wn = (warp >> 1) << 6;   // 2 warps over N (2 x 64)

    const int lr = tid >> 3;           // cp.async row base 0..15
    const int lc = tid & 7;            // cp.async 16B-group  0..7
    const int KT = K >> 5;

    // ldmatrix lane decode
    const int a_ro = (((lane >> 3) & 1) << 3) + (lane & 7);
    const int a_co = lane >> 4;
    const int b_no = (((lane >> 4) & 1) << 3) + (lane & 7);
    const int b_co = (lane >> 3) & 1;

    float acc[4][8][4];
#pragma unroll
    for (int i = 0; i < 4; ++i)
#pragma unroll
        for (int j = 0; j < 8; ++j) {
            acc[i][j][0] = 0.f; acc[i][j][1] = 0.f;
            acc[i][j][2] = 0.f; acc[i][j][3] = 0.f;
        }

    const float* Abase = A + (size_t)bm * K;
    const float* Wbase = W + (size_t)bn * K;

    // Prologue: fill stages 0..1
#pragma unroll
    for (int p = 0; p < 2; ++p) {
        gemm_load_tiles(smem + p * STAGE_F, Abase + (p << 5), Wbase + (p << 5),
                        K, lr, lc);
        cp_commit();
    }
    cp_wait<1>();            // stage 0 resident
    __syncthreads();

    uint32_t af[2][4][4], bf[2][8][2];
    load_frags(af[0], bf[0], smem, 0, wm, wn, a_ro, a_co, b_no, b_co);
    int cur = 0;

    int s_cur = 0;                       // stage of tile kt (mod 3)
    for (int kt = 0; kt < KT; ++kt) {
        const float* as = smem + s_cur * STAGE_F;
        const int s_nxt = (s_cur + 1 == 3) ? 0 : s_cur + 1;   // stage of kt+1
        const int s_fre = s_cur ? s_cur - 1 : 2;              // (s_cur+2)%3 — held kt-1

#pragma unroll
        for (int ks = 0; ks < 3; ++ks) {
            load_frags(af[cur ^ 1], bf[cur ^ 1], as, ks + 1,
                       wm, wn, a_ro, a_co, b_no, b_co);
            mma_all(acc, af[cur], bf[cur]);
            cur ^= 1;
        }

        if (kt + 1 < KT) {
            // issue load of tile kt+2 into the stage freed when kt-1 finished
            if (kt + 2 < KT)
                gemm_load_tiles(smem + s_fre * STAGE_F,
                                Abase + ((kt + 2) << 5), Wbase + ((kt + 2) << 5),
                                K, lr, lc);
            cp_commit();
            cp_wait<1>();                 // tile kt+1 resident
            __syncthreads();
            // preload next tile's ks=0 fragments; ks=3 MMA below overlaps it
            load_frags(af[cur ^ 1], bf[cur ^ 1],
                       smem + s_nxt * STAGE_F, 0,
                       wm, wn, a_ro, a_co, b_no, b_co);
        }
        mma_all(acc, af[cur], bf[cur]);    // ks = 3
        cur ^= 1;
        s_cur = s_nxt;
    }

    // epilogue: bias (+gelu) + 8B stores
    const int g  = lane >> 2;
    const int tg = lane & 3;
#pragma unroll
    for (int mi = 0; mi < 4; ++mi) {
        int r0 = bm + wm + (mi << 4) + g;
#pragma unroll
        for (int nj = 0; nj < 8; ++nj) {
            int col = bn + wn + (nj << 3) + (tg << 1);
            float b0 = bias[col], b1 = bias[col + 1];
            float v0 = acc[mi][nj][0] + b0;
            float v1 = acc[mi][nj][1] + b1;
            float v2 = acc[mi][nj][2] + b0;
            float v3 = acc[mi][nj][3] + b1;
            if (GELU) {
                v0 *= normcdff(v0);
                v1 *= normcdff(v1);
                v2 *= normcdff(v2);
                v3 *= normcdff(v3);
            }
            *(float2*)(C + (size_t)r0 * N + col)       = make_float2(v0, v1);
            *(float2*)(C + (size_t)(r0 + 8) * N + col) = make_float2(v2, v3);
        }
    }
}

// ---------------------------------------------------------------------------
// Per-token head attention: 16x16 scores over heads, softmax, attn @ v.
// One CTA (128 threads) per token. Memory-bound.
// ---------------------------------------------------------------------------
__global__ void __launch_bounds__(128) attn_kernel(
    const float* __restrict__ QK, const float* __restrict__ V,
    float* __restrict__ O)
{
    const int t   = blockIdx.x;
    const int tid = threadIdx.x;
    __shared__ float qs[1024], ks2[1024], vs[1024], at[256];

    const float4* qk4 = (const float4*)(QK + (size_t)t * 2048);
    const float4* v4  = (const float4*)(V  + (size_t)t * 1024);
#pragma unroll
    for (int i = tid; i < 256; i += 128) {
        ((float4*)qs )[i] = qk4[i];
        ((float4*)ks2)[i] = qk4[256 + i];
        ((float4*)vs )[i] = v4[i];
    }
    __syncthreads();

#pragma unroll
    for (int sidx = tid; sidx < 256; sidx += 128) {
        int h = sidx >> 4, gg = sidx & 15;
        const float4* qp = (const float4*)(qs  + h  * 64);
        const float4* kp = (const float4*)(ks2 + gg * 64);
        float a = 0.f;
#pragma unroll
        for (int d = 0; d < 16; ++d) {
            float4 x = qp[d], y = kp[d];
            a += x.x * y.x + x.y * y.y + x.z * y.z + x.w * y.w;
        }
        at[sidx] = a * 0.125f;
    }
    __syncthreads();

    if (tid < 16) {
        float m = -1e30f;
#pragma unroll
        for (int gg = 0; gg < 16; ++gg) m = fmaxf(m, at[tid * 16 + gg]);
        float s = 0.f;
#pragma unroll
        for (int gg = 0; gg < 16; ++gg) {
            float e = expf(at[tid * 16 + gg] - m);
            at[tid * 16 + gg] = e;
            s += e;
        }
        float inv = 1.f / s;
#pragma unroll
        for (int gg = 0; gg < 16; ++gg) at[tid * 16 + gg] *= inv;
    }
    __syncthreads();

    float* out = O + (size_t)t * 1024;
#pragma unroll
    for (int o = tid; o < 1024; o += 128) {
        int h = o >> 6, d = o & 63;
        float a = 0.f;
#pragma unroll
        for (int gg = 0; gg < 16; ++gg) a += at[h * 16 + gg] * vs[gg * 64 + d];
        out[o] = a;
    }
}

// ---------------------------------------------------------------------------
// LayerNorm of (P + X) over last dim 1024, scale g, shift b.
// One warp per token; row lives in registers.
// ---------------------------------------------------------------------------
__global__ void __launch_bounds__(256) ln_kernel(
    const float* __restrict__ P, const float* __restrict__ X,
    const float* __restrict__ gw, const float* __restrict__ bw,
    float* __restrict__ O)
{
    const int t    = blockIdx.x * 8 + (threadIdx.x >> 5);
    const int lane = threadIdx.x & 31;
    const float4* p4 = (const float4*)(P + (size_t)t * 1024);
    const float4* x4 = (const float4*)(X + (size_t)t * 1024);

    float4 v[8];
    float s = 0.f;
#pragma unroll
    for (int j = 0; j < 8; ++j) {
        float4 a = p4[lane + (j << 5)];
        float4 c = x4[lane + (j << 5)];
        v[j].x = a.x + c.x; v[j].y = a.y + c.y;
        v[j].z = a.z + c.z; v[j].w = a.w + c.w;
        s += v[j].x + v[j].y + v[j].z + v[j].w;
    }
#pragma unroll
    for (int o = 16; o > 0; o >>= 1) s += __shfl_xor_sync(0xffffffffu, s, o);
    const float mu = s * (1.0f / 1024.0f);

    float q = 0.f;
#pragma unroll
    for (int j = 0; j < 8; ++j) {
        float dx;
        dx = v[j].x - mu; q += dx * dx;
        dx = v[j].y - mu; q += dx * dx;
        dx = v[j].z - mu; q += dx * dx;
        dx = v[j].w - mu; q += dx * dx;
    }
#pragma unroll
    for (int o = 16; o > 0; o >>= 1) q += __shfl_xor_sync(0xffffffffu, q, o);
    const float r = rsqrtf(q * (1.0f / 1024.0f) + 1e-5f);

    const float4* g4 = (const float4*)gw;
    const float4* b4 = (const float4*)bw;
    float4* o4 = (float4*)(O + (size_t)t * 1024);
#pragma unroll
    for (int j = 0; j < 8; ++j) {
        int i = lane + (j << 5);
        float4 gg = g4[i], bb = b4[i], ov;
        ov.x = (v[j].x - mu) * r * gg.x + bb.x;
        ov.y = (v[j].y - mu) * r * gg.y + bb.y;
        ov.z = (v[j].z - mu) * r * gg.z + bb.z;
        ov.w = (v[j].w - mu) * r * gg.w + bb.w;
        o4[i] = ov;
    }
}

// ---------------------------------------------------------------------------
// Launch
// ---------------------------------------------------------------------------
extern "C" void kernel_launch(void* const* d_in, const int* in_sizes, int n_in,
                              void* d_out, int out_size)
{
    const float* x      = (const float*)d_in[0];
    const float* qk_w   = (const float*)d_in[1];
    const float* qk_b   = (const float*)d_in[2];
    const float* v_w    = (const float*)d_in[3];
    const float* v_b    = (const float*)d_in[4];
    const float* proj_w = (const float*)d_in[5];
    const float* proj_b = (const float*)d_in[6];
    const float* ff_w   = (const float*)d_in[7];
    const float* ff_b   = (const float*)d_in[8];
    const float* ln_g   = (const float*)d_in[9];
    const float* ln_b   = (const float*)d_in[10];
    float* out = (float*)d_out;
    (void)in_sizes; (void)n_in; (void)out_size;

    cudaFuncSetAttribute(gemm_tf32<false>,
                         cudaFuncAttributeMaxDynamicSharedMemorySize, GSMEM);
    cudaFuncSetAttribute(gemm_tf32<true>,
                         cudaFuncAttributeMaxDynamicSharedMemorySize, GSMEM);

    float *qk, *v, *ao, *p, *h, *f;
    cudaGetSymbolAddress((void**)&qk, g_qk);
    cudaGetSymbolAddress((void**)&v,  g_v);
    cudaGetSymbolAddress((void**)&ao, g_ao);
    cudaGetSymbolAddress((void**)&p,  g_p);
    cudaGetSymbolAddress((void**)&h,  g_h);
    cudaGetSymbolAddress((void**)&f,  g_f);

    const dim3 blk(128);

    // 1-2: QKV projections
    gemm_tf32<false><<<dim3(N_QK / 128, M_TOK / 128), blk, GSMEM>>>(
        x, qk_w, qk_b, qk, M_TOK, N_QK, K_E);
    gemm_tf32<false><<<dim3(K_E / 128, M_TOK / 128), blk, GSMEM>>>(
        x, v_w, v_b, v, M_TOK, K_E, K_E);

    // 3: per-token head attention
    attn_kernel<<<M_TOK, 128>>>(qk, v, ao);

    // 4: output projection
    gemm_tf32<false><<<dim3(K_E / 128, M_TOK / 128), blk, GSMEM>>>(
        ao, proj_w, proj_b, p, M_TOK, K_E, K_E);

    // 5: h = LN(p + x)
    ln_kernel<<<M_TOK / 8, 256>>>(p, x, ln_g, ln_b, h);

    // 6: f = gelu(h @ ff_w^T + ff_b)
    gemm_tf32<true><<<dim3(K_E / 128, M_TOK / 128), blk, GSMEM>>>(
        h, ff_w, ff_b, f, M_TOK, K_E, K_E);

    // 7: out = LN(f + x)
    ln_kernel<<<M_TOK / 8, 256>>>(f, x, ln_g, ln_b, out);
}

// round 12
// speedup vs baseline: 1.3266x; 1.1043x over previous
#include <cuda_runtime.h>
#include <cuda_bf16.h>
#include <cstdint>

// ---------------------------------------------------------------------------
// Problem dims (fixed by the reference): E=1024, H=16, DQ=DV=64, B=8, S=4096
// ---------------------------------------------------------------------------
#define M_TOK 32768      // B*S tokens
#define K_E   1024       // embedding dim
#define N_QK  2048       // H*(DQ+DQ)

// ---------------------------------------------------------------------------
// Scratch (static __device__ — no runtime allocation allowed)
// ---------------------------------------------------------------------------
__device__ float g_qk[(size_t)M_TOK * N_QK];
__device__ float g_v [(size_t)M_TOK * K_E];
__device__ float g_ao[(size_t)M_TOK * K_E];
__device__ float g_p [(size_t)M_TOK * K_E];
__device__ float g_h [(size_t)M_TOK * K_E];
__device__ float g_f [(size_t)M_TOK * K_E];

// ---------------------------------------------------------------------------
// PTX helpers (plain sm_103 target: no 'a'-features, mma.sync tf32 path)
// ---------------------------------------------------------------------------
__device__ __forceinline__ uint32_t smem_u32(const void* p) {
    return (uint32_t)__cvta_generic_to_shared(p);
}
__device__ __forceinline__ void cp_async16(uint32_t dst, const void* src) {
    asm volatile("cp.async.cg.shared.global [%0], [%1], 16;\n" :: "r"(dst), "l"(src));
}
__device__ __forceinline__ void cp_commit() {
    asm volatile("cp.async.commit_group;\n");
}
template <int N>
__device__ __forceinline__ void cp_wait() {
    asm volatile("cp.async.wait_group %0;\n" :: "n"(N));
}
__device__ __forceinline__ void ldsm_x4(uint32_t* r, uint32_t a) {
    asm volatile("ldmatrix.sync.aligned.m8n8.x4.shared.b16 {%0,%1,%2,%3}, [%4];\n"
                 : "=r"(r[0]), "=r"(r[1]), "=r"(r[2]), "=r"(r[3]) : "r"(a));
}
__device__ __forceinline__ void mma_tf32(float* d, const uint32_t* a, const uint32_t* b) {
    asm volatile("mma.sync.aligned.m16n8k8.row.col.f32.tf32.tf32.f32 "
                 "{%0,%1,%2,%3}, {%4,%5,%6,%7}, {%8,%9}, {%0,%1,%2,%3};\n"
                 : "+f"(d[0]), "+f"(d[1]), "+f"(d[2]), "+f"(d[3])
                 : "r"(a[0]), "r"(a[1]), "r"(a[2]), "r"(a[3]),
                   "r"(b[0]), "r"(b[1]));
}

// ---------------------------------------------------------------------------
// tf32 GEMM (unchanged from R10 winner): C = A @ W^T + bias  (opt GELU)
// BM=128, BN=128, BK=32. 128 threads = 4 warps (2x2), warp tile 64x64.
// 2 CTAs/SM, 3-stage cp.async pipeline, one __syncthreads per k-tile,
// register-fragment double buffering with cross-tile ks=0 preload.
// ---------------------------------------------------------------------------
#define STAGE_F 8192                 // floats per stage: 4096 A + 4096 B
#define GSMEM   (3 * STAGE_F * 4)    // 98304 bytes

__device__ __forceinline__ void gemm_load_tiles(
    float* as, const float* Ag, const float* Wg, int K, int lr, int lc)
{
    float* bs = as + 4096;
#pragma unroll
    for (int i = 0; i < 8; ++i) {            // A: 128 rows, 16 rows/pass
        int row = lr + (i << 4);
        int sw  = ((lc ^ (row & 7)) << 2);
        cp_async16(smem_u32(as + row * 32 + sw), Ag + (size_t)row * K + (lc << 2));
    }
#pragma unroll
    for (int i = 0; i < 8; ++i) {            // B: 128 rows
        int row = lr + (i << 4);
        int sw  = ((lc ^ (row & 7)) << 2);
        cp_async16(smem_u32(bs + row * 32 + sw), Wg + (size_t)row * K + (lc << 2));
    }
}

__device__ __forceinline__ void load_frags(
    uint32_t af[4][4], uint32_t bf[8][2], const float* as, int ks,
    int wm, int wn, int a_ro, int a_co, int b_no, int b_co)
{
    const float* bs = as + 4096;
    const int cgb = ks << 1;
#pragma unroll
    for (int mi = 0; mi < 4; ++mi) {
        int row = wm + (mi << 4) + a_ro;
        int cg  = cgb + a_co;
        ldsm_x4(af[mi], smem_u32(as + row * 32 + ((cg ^ (row & 7)) << 2)));
    }
#pragma unroll
    for (int jj = 0; jj < 4; ++jj) {
        int n  = wn + (jj << 4) + b_no;
        int cg = cgb + b_co;
        uint32_t t[4];
        ldsm_x4(t, smem_u32(bs + n * 32 + ((cg ^ (n & 7)) << 2)));
        bf[jj * 2    ][0] = t[0]; bf[jj * 2    ][1] = t[1];
        bf[jj * 2 + 1][0] = t[2]; bf[jj * 2 + 1][1] = t[3];
    }
}

__device__ __forceinline__ void mma_all(
    float acc[4][8][4], uint32_t af[4][4], uint32_t bf[8][2])
{
#pragma unroll
    for (int mi = 0; mi < 4; ++mi)
#pragma unroll
        for (int nj = 0; nj < 8; ++nj)
            mma_tf32(acc[mi][nj], af[mi], bf[nj]);
}

template <bool GELU>
__global__ void __launch_bounds__(128, 2) gemm_tf32(
    const float* __restrict__ A, const float* __restrict__ W,
    const float* __restrict__ bias, float* __restrict__ C,
    int M, int N, int K)
{
    extern __shared__ float smem[];   // 3 stages x 8192 floats = 96 KB

    const int tid  = threadIdx.x;
    const int lane = tid & 31;
    const int warp = tid >> 5;
    const int bm = blockIdx.y << 7;
    const int bn = blockIdx.x << 7;
    const int wm = (warp & 1) << 6;    // 2 warps over M (2 x 64)
    const int wn = (warp >> 1) << 6;   // 2 warps over N (2 x 64)

    const int lr = tid >> 3;           // cp.async row base 0..15
    const int lc = tid & 7;            // cp.async 16B-group  0..7
    const int KT = K >> 5;

    // ldmatrix lane decode
    const int a_ro = (((lane >> 3) & 1) << 3) + (lane & 7);
    const int a_co = lane >> 4;
    const int b_no = (((lane >> 4) & 1) << 3) + (lane & 7);
    const int b_co = (lane >> 3) & 1;

    float acc[4][8][4];
#pragma unroll
    for (int i = 0; i < 4; ++i)
#pragma unroll
        for (int j = 0; j < 8; ++j) {
            acc[i][j][0] = 0.f; acc[i][j][1] = 0.f;
            acc[i][j][2] = 0.f; acc[i][j][3] = 0.f;
        }

    const float* Abase = A + (size_t)bm * K;
    const float* Wbase = W + (size_t)bn * K;

    // Prologue: fill stages 0..1
#pragma unroll
    for (int p = 0; p < 2; ++p) {
        gemm_load_tiles(smem + p * STAGE_F, Abase + (p << 5), Wbase + (p << 5),
                        K, lr, lc);
        cp_commit();
    }
    cp_wait<1>();            // stage 0 resident
    __syncthreads();

    uint32_t af[2][4][4], bf[2][8][2];
    load_frags(af[0], bf[0], smem, 0, wm, wn, a_ro, a_co, b_no, b_co);
    int cur = 0;

    int s_cur = 0;                       // stage of tile kt (mod 3)
    for (int kt = 0; kt < KT; ++kt) {
        const float* as = smem + s_cur * STAGE_F;
        const int s_nxt = (s_cur + 1 == 3) ? 0 : s_cur + 1;   // stage of kt+1
        const int s_fre = s_cur ? s_cur - 1 : 2;              // (s_cur+2)%3 — held kt-1

#pragma unroll
        for (int ks = 0; ks < 3; ++ks) {
            load_frags(af[cur ^ 1], bf[cur ^ 1], as, ks + 1,
                       wm, wn, a_ro, a_co, b_no, b_co);
            mma_all(acc, af[cur], bf[cur]);
            cur ^= 1;
        }

        if (kt + 1 < KT) {
            // issue load of tile kt+2 into the stage freed when kt-1 finished
            if (kt + 2 < KT)
                gemm_load_tiles(smem + s_fre * STAGE_F,
                                Abase + ((kt + 2) << 5), Wbase + ((kt + 2) << 5),
                                K, lr, lc);
            cp_commit();
            cp_wait<1>();                 // tile kt+1 resident
            __syncthreads();
            // preload next tile's ks=0 fragments; ks=3 MMA below overlaps it
            load_frags(af[cur ^ 1], bf[cur ^ 1],
                       smem + s_nxt * STAGE_F, 0,
                       wm, wn, a_ro, a_co, b_no, b_co);
        }
        mma_all(acc, af[cur], bf[cur]);    // ks = 3
        cur ^= 1;
        s_cur = s_nxt;
    }

    // epilogue: bias (+gelu) + 8B stores
    const int g  = lane >> 2;
    const int tg = lane & 3;
#pragma unroll
    for (int mi = 0; mi < 4; ++mi) {
        int r0 = bm + wm + (mi << 4) + g;
#pragma unroll
        for (int nj = 0; nj < 8; ++nj) {
            int col = bn + wn + (nj << 3) + (tg << 1);
            float b0 = bias[col], b1 = bias[col + 1];
            float v0 = acc[mi][nj][0] + b0;
            float v1 = acc[mi][nj][1] + b1;
            float v2 = acc[mi][nj][2] + b0;
            float v3 = acc[mi][nj][3] + b1;
            if (GELU) {
                v0 *= normcdff(v0);
                v1 *= normcdff(v1);
                v2 *= normcdff(v2);
                v3 *= normcdff(v3);
            }
            *(float2*)(C + (size_t)r0 * N + col)       = make_float2(v0, v1);
            *(float2*)(C + (size_t)(r0 + 8) * N + col) = make_float2(v2, v3);
        }
    }
}

// ---------------------------------------------------------------------------
// Per-token head attention: 16x16 scores over heads, softmax, attn @ v.
// One CTA (128 threads) per token.
// R11: bank-conflict fixes. k rows padded to stride 68 floats — the score
// loop's 16 lanes (distinct g, same d) previously all hit the same bank
// (stride 64 ⇒ 16-way conflict per LDS.128); stride 68 gives banks 4(g+d)%32
// = 2-way, the LDS.128 structural floor. at[] padded to stride 17 (softmax
// row sweep was 8-way at stride 16). Arithmetic and summation order identical.
// ---------------------------------------------------------------------------
#define KSTR 68    // padded k-row stride (floats)
#define ASTR 17    // padded attn-row stride (floats)

__global__ void __launch_bounds__(128) attn_kernel(
    const float* __restrict__ QK, const float* __restrict__ V,
    float* __restrict__ O)
{
    const int t   = blockIdx.x;
    const int tid = threadIdx.x;
    __shared__ float qs[1024], ks2[15 * KSTR + 64 + 4], vs[1024], at[16 * ASTR];

    const float4* qk4 = (const float4*)(QK + (size_t)t * 2048);
    const float4* v4  = (const float4*)(V  + (size_t)t * 1024);
#pragma unroll
    for (int i = tid; i < 256; i += 128) {
        ((float4*)qs)[i] = qk4[i];
        float4 kv = qk4[256 + i];
        int kg = i >> 4, kc = i & 15;                  // k row, 16B chunk
        *(float4*)(ks2 + kg * KSTR + (kc << 2)) = kv;
        ((float4*)vs)[i] = v4[i];
    }
    __syncthreads();

    // 256 scores, 2 per thread: s(h,g) = q[h]·k[g] / 8
#pragma unroll
    for (int sidx = tid; sidx < 256; sidx += 128) {
        int h = sidx >> 4, gg = sidx & 15;
        const float4* qp = (const float4*)(qs  + h  * 64);
        const float4* kp = (const float4*)(ks2 + gg * KSTR);
        float a = 0.f;
#pragma unroll
        for (int d = 0; d < 16; ++d) {
            float4 x = qp[d], y = kp[d];
            a += x.x * y.x + x.y * y.y + x.z * y.z + x.w * y.w;
        }
        at[h * ASTR + gg] = a * 0.125f;
    }
    __syncthreads();

    if (tid < 16) {
        float m = -1e30f;
#pragma unroll
        for (int gg = 0; gg < 16; ++gg) m = fmaxf(m, at[tid * ASTR + gg]);
        float s = 0.f;
#pragma unroll
        for (int gg = 0; gg < 16; ++gg) {
            float e = expf(at[tid * ASTR + gg] - m);
            at[tid * ASTR + gg] = e;
            s += e;
        }
        float inv = 1.f / s;
#pragma unroll
        for (int gg = 0; gg < 16; ++gg) at[tid * ASTR + gg] *= inv;
    }
    __syncthreads();

    float* out = O + (size_t)t * 1024;
#pragma unroll
    for (int o = tid; o < 1024; o += 128) {
        int h = o >> 6, d = o & 63;
        float a = 0.f;
#pragma unroll
        for (int gg = 0; gg < 16; ++gg) a += at[h * ASTR + gg] * vs[gg * 64 + d];
        out[o] = a;
    }
}

// ---------------------------------------------------------------------------
// LayerNorm of (P + X) over last dim 1024, scale g, shift b.
// One warp per token; row lives in registers.
// ---------------------------------------------------------------------------
__global__ void __launch_bounds__(256) ln_kernel(
    const float* __restrict__ P, const float* __restrict__ X,
    const float* __restrict__ gw, const float* __restrict__ bw,
    float* __restrict__ O)
{
    const int t    = blockIdx.x * 8 + (threadIdx.x >> 5);
    const int lane = threadIdx.x & 31;
    const float4* p4 = (const float4*)(P + (size_t)t * 1024);
    const float4* x4 = (const float4*)(X + (size_t)t * 1024);

    float4 v[8];
    float s = 0.f;
#pragma unroll
    for (int j = 0; j < 8; ++j) {
        float4 a = p4[lane + (j << 5)];
        float4 c = x4[lane + (j << 5)];
        v[j].x = a.x + c.x; v[j].y = a.y + c.y;
        v[j].z = a.z + c.z; v[j].w = a.w + c.w;
        s += v[j].x + v[j].y + v[j].z + v[j].w;
    }
#pragma unroll
    for (int o = 16; o > 0; o >>= 1) s += __shfl_xor_sync(0xffffffffu, s, o);
    const float mu = s * (1.0f / 1024.0f);

    float q = 0.f;
#pragma unroll
    for (int j = 0; j < 8; ++j) {
        float dx;
        dx = v[j].x - mu; q += dx * dx;
        dx = v[j].y - mu; q += dx * dx;
        dx = v[j].z - mu; q += dx * dx;
        dx = v[j].w - mu; q += dx * dx;
    }
#pragma unroll
    for (int o = 16; o > 0; o >>= 1) q += __shfl_xor_sync(0xffffffffu, q, o);
    const float r = rsqrtf(q * (1.0f / 1024.0f) + 1e-5f);

    const float4* g4 = (const float4*)gw;
    const float4* b4 = (const float4*)bw;
    float4* o4 = (float4*)(O + (size_t)t * 1024);
#pragma unroll
    for (int j = 0; j < 8; ++j) {
        int i = lane + (j << 5);
        float4 gg = g4[i], bb = b4[i], ov;
        ov.x = (v[j].x - mu) * r * gg.x + bb.x;
        ov.y = (v[j].y - mu) * r * gg.y + bb.y;
        ov.z = (v[j].z - mu) * r * gg.z + bb.z;
        ov.w = (v[j].w - mu) * r * gg.w + bb.w;
        o4[i] = ov;
    }
}

// ---------------------------------------------------------------------------
// Launch
// ---------------------------------------------------------------------------
extern "C" void kernel_launch(void* const* d_in, const int* in_sizes, int n_in,
                              void* d_out, int out_size)
{
    const float* x      = (const float*)d_in[0];
    const float* qk_w   = (const float*)d_in[1];
    const float* qk_b   = (const float*)d_in[2];
    const float* v_w    = (const float*)d_in[3];
    const float* v_b    = (const float*)d_in[4];
    const float* proj_w = (const float*)d_in[5];
    const float* proj_b = (const float*)d_in[6];
    const float* ff_w   = (const float*)d_in[7];
    const float* ff_b   = (const float*)d_in[8];
    const float* ln_g   = (const float*)d_in[9];
    const float* ln_b   = (const float*)d_in[10];
    float* out = (float*)d_out;
    (void)in_sizes; (void)n_in; (void)out_size;

    cudaFuncSetAttribute(gemm_tf32<false>,
                         cudaFuncAttributeMaxDynamicSharedMemorySize, GSMEM);
    cudaFuncSetAttribute(gemm_tf32<true>,
                         cudaFuncAttributeMaxDynamicSharedMemorySize, GSMEM);

    float *qk, *v, *ao, *p, *h, *f;
    cudaGetSymbolAddress((void**)&qk, g_qk);
    cudaGetSymbolAddress((void**)&v,  g_v);
    cudaGetSymbolAddress((void**)&ao, g_ao);
    cudaGetSymbolAddress((void**)&p,  g_p);
    cudaGetSymbolAddress((void**)&h,  g_h);
    cudaGetSymbolAddress((void**)&f,  g_f);

    const dim3 blk(128);

    // 1-2: QKV projections
    gemm_tf32<false><<<dim3(N_QK / 128, M_TOK / 128), blk, GSMEM>>>(
        x, qk_w, qk_b, qk, M_TOK, N_QK, K_E);
    gemm_tf32<false><<<dim3(K_E / 128, M_TOK / 128), blk, GSMEM>>>(
        x, v_w, v_b, v, M_TOK, K_E, K_E);

    // 3: per-token head attention
    attn_kernel<<<M_TOK, 128>>>(qk, v, ao);

    // 4: output projection
    gemm_tf32<false><<<dim3(K_E / 128, M_TOK / 128), blk, GSMEM>>>(
        ao, proj_w, proj_b, p, M_TOK, K_E, K_E);

    // 5: h = LN(p + x)
    ln_kernel<<<M_TOK / 8, 256>>>(p, x, ln_g, ln_b, h);

    // 6: f = gelu(h @ ff_w^T + ff_b)
    gemm_tf32<true><<<dim3(K_E / 128, M_TOK / 128), blk, GSMEM>>>(
        h, ff_w, ff_b, f, M_TOK, K_E, K_E);

    // 7: out = LN(f + x)
    ln_kernel<<<M_TOK / 8, 256>>>(f, x, ln_g, ln_b, out);
}

// round 13
// speedup vs baseline: 1.8684x; 1.4084x over previous
#include <cuda_runtime.h>
#include <cuda_fp16.h>
#include <cstdint>

// ---------------------------------------------------------------------------
// Problem dims (fixed by the reference): E=1024, H=16, DQ=DV=64, B=8, S=4096
// ---------------------------------------------------------------------------
#define M_TOK 32768      // B*S tokens
#define K_E   1024       // embedding dim
#define N_QK  2048       // H*(DQ+DQ)

// ---------------------------------------------------------------------------
// Scratch (static __device__ — no runtime allocation allowed)
// ---------------------------------------------------------------------------
__device__ float  g_qk[(size_t)M_TOK * N_QK];    // fp32 (attn input)
__device__ float  g_v [(size_t)M_TOK * K_E];     // fp32 (attn input)
__device__ float  g_p [(size_t)M_TOK * K_E];     // fp32 (LN1 input)
__device__ float  g_f [(size_t)M_TOK * K_E];     // fp32 (LN2 input)
__device__ __half g_xh [(size_t)M_TOK * K_E];    // fp16 GEMM inputs
__device__ __half g_aoh[(size_t)M_TOK * K_E];
__device__ __half g_hh [(size_t)M_TOK * K_E];
__device__ __half g_wqk[(size_t)N_QK * K_E];     // fp16 weights
__device__ __half g_wv [(size_t)K_E * K_E];
__device__ __half g_wp [(size_t)K_E * K_E];
__device__ __half g_wf [(size_t)K_E * K_E];

// ---------------------------------------------------------------------------
// PTX helpers (plain sm_103 target: no 'a'-features; legacy mma.sync path.
// fp16 m16n8k16 has the SAME 11-bit mantissa as tf32 but 2x the MAC rate)
// ---------------------------------------------------------------------------
__device__ __forceinline__ uint32_t smem_u32(const void* p) {
    return (uint32_t)__cvta_generic_to_shared(p);
}
__device__ __forceinline__ void cp_async16(uint32_t dst, const void* src) {
    asm volatile("cp.async.cg.shared.global [%0], [%1], 16;\n" :: "r"(dst), "l"(src));
}
__device__ __forceinline__ void cp_commit() {
    asm volatile("cp.async.commit_group;\n");
}
template <int N>
__device__ __forceinline__ void cp_wait() {
    asm volatile("cp.async.wait_group %0;\n" :: "n"(N));
}
__device__ __forceinline__ void ldsm_x4(uint32_t* r, uint32_t a) {
    asm volatile("ldmatrix.sync.aligned.m8n8.x4.shared.b16 {%0,%1,%2,%3}, [%4];\n"
                 : "=r"(r[0]), "=r"(r[1]), "=r"(r[2]), "=r"(r[3]) : "r"(a));
}
__device__ __forceinline__ void mma_f16(float* d, const uint32_t* a, const uint32_t* b) {
    asm volatile("mma.sync.aligned.m16n8k16.row.col.f32.f16.f16.f32 "
                 "{%0,%1,%2,%3}, {%4,%5,%6,%7}, {%8,%9}, {%0,%1,%2,%3};\n"
                 : "+f"(d[0]), "+f"(d[1]), "+f"(d[2]), "+f"(d[3])
                 : "r"(a[0]), "r"(a[1]), "r"(a[2]), "r"(a[3]),
                   "r"(b[0]), "r"(b[1]));
}

// ---------------------------------------------------------------------------
// fp32 -> fp16 conversion (vectorized, 8 elems/thread)
// ---------------------------------------------------------------------------
__global__ void __launch_bounds__(256) cvt_f2h(
    const float* __restrict__ in, __half* __restrict__ out, int n)
{
    int i = (blockIdx.x * 256 + threadIdx.x) << 3;
    if (i >= n) return;
    float4 a = *(const float4*)(in + i);
    float4 b = *(const float4*)(in + i + 4);
    __half2 h0 = __floats2half2_rn(a.x, a.y);
    __half2 h1 = __floats2half2_rn(a.z, a.w);
    __half2 h2 = __floats2half2_rn(b.x, b.y);
    __half2 h3 = __floats2half2_rn(b.z, b.w);
    uint4 u;
    u.x = *(uint32_t*)&h0; u.y = *(uint32_t*)&h1;
    u.z = *(uint32_t*)&h2; u.w = *(uint32_t*)&h3;
    *(uint4*)(out + i) = u;
}

// ---------------------------------------------------------------------------
// fp16 GEMM: C[M,N](fp32) = A[M,K]h @ W[N,K]h^T + bias[N]  (opt exact GELU)
// BM=128, BN=128, BK=64 halves (128B/row, same SW-XOR swizzle as proven code).
// 128 threads = 4 warps (2x2), warp tile 64x64. 2 CTAs/SM, 3-stage cp.async
// pipeline (96 KB), one __syncthreads per k-tile, fragment double buffering
// with cross-tile ks=0 preload. Per ks (k16): 8 LDSM.x4 -> 32 HMMA.16816.
// ---------------------------------------------------------------------------
#define STAGE_F 8192                 // uint32 per stage: 4096 A + 4096 B
#define GSMEM   (3 * STAGE_F * 4)    // 98304 bytes

__device__ __forceinline__ void gemm_load_tiles(
    float* as, const __half* Ag, const __half* Wg, int K, int lr, int lc)
{
    float* bs = as + 4096;
#pragma unroll
    for (int i = 0; i < 8; ++i) {            // A: 128 rows, 16 rows/pass
        int row = lr + (i << 4);
        int sw  = ((lc ^ (row & 7)) << 2);
        cp_async16(smem_u32(as + row * 32 + sw), Ag + (size_t)row * K + (lc << 3));
    }
#pragma unroll
    for (int i = 0; i < 8; ++i) {            // B: 128 rows
        int row = lr + (i << 4);
        int sw  = ((lc ^ (row & 7)) << 2);
        cp_async16(smem_u32(bs + row * 32 + sw), Wg + (size_t)row * K + (lc << 3));
    }
}

// fp16 fragment loads. Decode (both A and B): ro = lane&15 row within 16,
// co = lane>>4 selects k0-7 vs k8-15 (16B). One ldsm.x4 covers 16 rows x k16.
__device__ __forceinline__ void load_frags(
    uint32_t af[4][4], uint32_t bf[8][2], const float* as, int ks,
    int wm, int wn, int ro, int co)
{
    const float* bs = as + 4096;
    const int cg = (ks << 1) + co;
#pragma unroll
    for (int mi = 0; mi < 4; ++mi) {
        int row = wm + (mi << 4) + ro;
        ldsm_x4(af[mi], smem_u32(as + row * 32 + ((cg ^ (row & 7)) << 2)));
    }
#pragma unroll
    for (int jj = 0; jj < 4; ++jj) {
        int n = wn + (jj << 4) + ro;
        uint32_t t[4];
        ldsm_x4(t, smem_u32(bs + n * 32 + ((cg ^ (n & 7)) << 2)));
        bf[jj * 2    ][0] = t[0]; bf[jj * 2    ][1] = t[2];   // n0-7 : k0-7, k8-15
        bf[jj * 2 + 1][0] = t[1]; bf[jj * 2 + 1][1] = t[3];   // n8-15
    }
}

__device__ __forceinline__ void mma_all(
    float acc[4][8][4], uint32_t af[4][4], uint32_t bf[8][2])
{
#pragma unroll
    for (int mi = 0; mi < 4; ++mi)
#pragma unroll
        for (int nj = 0; nj < 8; ++nj)
            mma_f16(acc[mi][nj], af[mi], bf[nj]);
}

template <bool GELU>
__global__ void __launch_bounds__(128, 2) gemm_f16(
    const __half* __restrict__ A, const __half* __restrict__ W,
    const float* __restrict__ bias, float* __restrict__ C,
    int M, int N, int K)
{
    extern __shared__ float smem[];   // 3 stages x 8192 uint32 = 96 KB

    const int tid  = threadIdx.x;
    const int lane = tid & 31;
    const int warp = tid >> 5;
    const int bm = blockIdx.y << 7;
    const int bn = blockIdx.x << 7;
    const int wm = (warp & 1) << 6;    // 2 warps over M (2 x 64)
    const int wn = (warp >> 1) << 6;   // 2 warps over N (2 x 64)

    const int lr = tid >> 3;           // cp.async row base 0..15
    const int lc = tid & 7;            // cp.async 16B-group  0..7
    const int KT = K >> 6;             // 64 halves per k-tile

    // fp16 ldmatrix lane decode (A and B identical)
    const int ro = (((lane >> 3) & 1) << 3) + (lane & 7);
    const int co = lane >> 4;

    float acc[4][8][4];
#pragma unroll
    for (int i = 0; i < 4; ++i)
#pragma unroll
        for (int j = 0; j < 8; ++j) {
            acc[i][j][0] = 0.f; acc[i][j][1] = 0.f;
            acc[i][j][2] = 0.f; acc[i][j][3] = 0.f;
        }

    const __half* Abase = A + (size_t)bm * K;
    const __half* Wbase = W + (size_t)bn * K;

    // Prologue: fill stages 0..1
#pragma unroll
    for (int p = 0; p < 2; ++p) {
        gemm_load_tiles(smem + p * STAGE_F, Abase + (p << 6), Wbase + (p << 6),
                        K, lr, lc);
        cp_commit();
    }
    cp_wait<1>();            // stage 0 resident
    __syncthreads();

    uint32_t af[2][4][4], bf[2][8][2];
    load_frags(af[0], bf[0], smem, 0, wm, wn, ro, co);
    int cur = 0;

    int s_cur = 0;                       // stage of tile kt (mod 3)
    for (int kt = 0; kt < KT; ++kt) {
        const float* as = smem + s_cur * STAGE_F;
        const int s_nxt = (s_cur + 1 == 3) ? 0 : s_cur + 1;   // stage of kt+1
        const int s_fre = s_cur ? s_cur - 1 : 2;              // (s_cur+2)%3

#pragma unroll
        for (int ks = 0; ks < 3; ++ks) {
            load_frags(af[cur ^ 1], bf[cur ^ 1], as, ks + 1, wm, wn, ro, co);
            mma_all(acc, af[cur], bf[cur]);
            cur ^= 1;
        }

        if (kt + 1 < KT) {
            if (kt + 2 < KT)
                gemm_load_tiles(smem + s_fre * STAGE_F,
                                Abase + ((size_t)(kt + 2) << 6),
                                Wbase + ((size_t)(kt + 2) << 6),
                                K, lr, lc);
            cp_commit();
            cp_wait<1>();                 // tile kt+1 resident
            __syncthreads();
            load_frags(af[cur ^ 1], bf[cur ^ 1],
                       smem + s_nxt * STAGE_F, 0, wm, wn, ro, co);
        }
        mma_all(acc, af[cur], bf[cur]);    // ks = 3
        cur ^= 1;
        s_cur = s_nxt;
    }

    // epilogue: bias (+gelu) + 8B stores (acc layout same as tf32 path)
    const int g  = lane >> 2;
    const int tg = lane & 3;
#pragma unroll
    for (int mi = 0; mi < 4; ++mi) {
        int r0 = bm + wm + (mi << 4) + g;
#pragma unroll
        for (int nj = 0; nj < 8; ++nj) {
            int col = bn + wn + (nj << 3) + (tg << 1);
            float b0 = bias[col], b1 = bias[col + 1];
            float v0 = acc[mi][nj][0] + b0;
            float v1 = acc[mi][nj][1] + b1;
            float v2 = acc[mi][nj][2] + b0;
            float v3 = acc[mi][nj][3] + b1;
            if (GELU) {
                v0 *= normcdff(v0);
                v1 *= normcdff(v1);
                v2 *= normcdff(v2);
                v3 *= normcdff(v3);
            }
            *(float2*)(C + (size_t)r0 * N + col)       = make_float2(v0, v1);
            *(float2*)(C + (size_t)(r0 + 8) * N + col) = make_float2(v2, v3);
        }
    }
}

// ---------------------------------------------------------------------------
// Per-token head attention (R12 conflict-free layout); output now fp16
// (it feeds only the proj GEMM, whose inputs are rounded to fp16 anyway).
// ---------------------------------------------------------------------------
#define KSTR 68    // padded k-row stride (floats)
#define ASTR 17    // padded attn-row stride (floats)

__global__ void __launch_bounds__(128) attn_kernel(
    const float* __restrict__ QK, const float* __restrict__ V,
    __half* __restrict__ O)
{
    const int t   = blockIdx.x;
    const int tid = threadIdx.x;
    __shared__ float qs[1024], ks2[15 * KSTR + 64 + 4], vs[1024], at[16 * ASTR];

    const float4* qk4 = (const float4*)(QK + (size_t)t * 2048);
    const float4* v4  = (const float4*)(V  + (size_t)t * 1024);
#pragma unroll
    for (int i = tid; i < 256; i += 128) {
        ((float4*)qs)[i] = qk4[i];
        float4 kv = qk4[256 + i];
        int kg = i >> 4, kc = i & 15;
        *(float4*)(ks2 + kg * KSTR + (kc << 2)) = kv;
        ((float4*)vs)[i] = v4[i];
    }
    __syncthreads();

#pragma unroll
    for (int sidx = tid; sidx < 256; sidx += 128) {
        int h = sidx >> 4, gg = sidx & 15;
        const float4* qp = (const float4*)(qs  + h  * 64);
        const float4* kp = (const float4*)(ks2 + gg * KSTR);
        float a = 0.f;
#pragma unroll
        for (int d = 0; d < 16; ++d) {
            float4 x = qp[d], y = kp[d];
            a += x.x * y.x + x.y * y.y + x.z * y.z + x.w * y.w;
        }
        at[h * ASTR + gg] = a * 0.125f;
    }
    __syncthreads();

    if (tid < 16) {
        float m = -1e30f;
#pragma unroll
        for (int gg = 0; gg < 16; ++gg) m = fmaxf(m, at[tid * ASTR + gg]);
        float s = 0.f;
#pragma unroll
        for (int gg = 0; gg < 16; ++gg) {
            float e = expf(at[tid * ASTR + gg] - m);
            at[tid * ASTR + gg] = e;
            s += e;
        }
        float inv = 1.f / s;
#pragma unroll
        for (int gg = 0; gg < 16; ++gg) at[tid * ASTR + gg] *= inv;
    }
    __syncthreads();

    __half2* out = (__half2*)(O + (size_t)t * 1024);
#pragma unroll
    for (int oo = tid; oo < 512; oo += 128) {
        int o = oo << 1;
        int h = o >> 6, d = o & 63;
        float a0 = 0.f, a1 = 0.f;
#pragma unroll
        for (int gg = 0; gg < 16; ++gg) {
            float w = at[h * ASTR + gg];
            a0 += w * vs[gg * 64 + d];
            a1 += w * vs[gg * 64 + d + 1];
        }
        out[oo] = __floats2half2_rn(a0, a1);
    }
}

// ---------------------------------------------------------------------------
// LayerNorm of (P + X) over last dim 1024. One warp/token, row in registers.
// HALF_OUT writes fp16 (feeds FF GEMM); else fp32 (final output).
// ---------------------------------------------------------------------------
template <bool HALF_OUT>
__global__ void __launch_bounds__(256) ln_kernel(
    const float* __restrict__ P, const float* __restrict__ X,
    const float* __restrict__ gw, const float* __restrict__ bw,
    void* __restrict__ Optr)
{
    const int t    = blockIdx.x * 8 + (threadIdx.x >> 5);
    const int lane = threadIdx.x & 31;
    const float4* p4 = (const float4*)(P + (size_t)t * 1024);
    const float4* x4 = (const float4*)(X + (size_t)t * 1024);

    float4 v[8];
    float s = 0.f;
#pragma unroll
    for (int j = 0; j < 8; ++j) {
        float4 a = p4[lane + (j << 5)];
        float4 c = x4[lane + (j << 5)];
        v[j].x = a.x + c.x; v[j].y = a.y + c.y;
        v[j].z = a.z + c.z; v[j].w = a.w + c.w;
        s += v[j].x + v[j].y + v[j].z + v[j].w;
    }
#pragma unroll
    for (int o = 16; o > 0; o >>= 1) s += __shfl_xor_sync(0xffffffffu, s, o);
    const float mu = s * (1.0f / 1024.0f);

    float q = 0.f;
#pragma unroll
    for (int j = 0; j < 8; ++j) {
        float dx;
        dx = v[j].x - mu; q += dx * dx;
        dx = v[j].y - mu; q += dx * dx;
        dx = v[j].z - mu; q += dx * dx;
        dx = v[j].w - mu; q += dx * dx;
    }
#pragma unroll
    for (int o = 16; o > 0; o >>= 1) q += __shfl_xor_sync(0xffffffffu, q, o);
    const float r = rsqrtf(q * (1.0f / 1024.0f) + 1e-5f);

    const float4* g4 = (const float4*)gw;
    const float4* b4 = (const float4*)bw;
#pragma unroll
    for (int j = 0; j < 8; ++j) {
        int i = lane + (j << 5);
        float4 gg = g4[i], bb = b4[i], ov;
        ov.x = (v[j].x - mu) * r * gg.x + bb.x;
        ov.y = (v[j].y - mu) * r * gg.y + bb.y;
        ov.z = (v[j].z - mu) * r * gg.z + bb.z;
        ov.w = (v[j].w - mu) * r * gg.w + bb.w;
        if (HALF_OUT) {
            __half2 h0 = __floats2half2_rn(ov.x, ov.y);
            __half2 h1 = __floats2half2_rn(ov.z, ov.w);
            uint2 u;
            u.x = *(uint32_t*)&h0; u.y = *(uint32_t*)&h1;
            *(uint2*)((__half*)Optr + (size_t)t * 1024 + (i << 2)) = u;
        } else {
            *(float4*)((float*)Optr + (size_t)t * 1024 + (i << 2)) = ov;
        }
    }
}

// ---------------------------------------------------------------------------
// Launch
// ---------------------------------------------------------------------------
extern "C" void kernel_launch(void* const* d_in, const int* in_sizes, int n_in,
                              void* d_out, int out_size)
{
    const float* x      = (const float*)d_in[0];
    const float* qk_w   = (const float*)d_in[1];
    const float* qk_b   = (const float*)d_in[2];
    const float* v_w    = (const float*)d_in[3];
    const float* v_b    = (const float*)d_in[4];
    const float* proj_w = (const float*)d_in[5];
    const float* proj_b = (const float*)d_in[6];
    const float* ff_w   = (const float*)d_in[7];
    const float* ff_b   = (const float*)d_in[8];
    const float* ln_g   = (const float*)d_in[9];
    const float* ln_b   = (const float*)d_in[10];
    float* out = (float*)d_out;
    (void)in_sizes; (void)n_in; (void)out_size;

    cudaFuncSetAttribute(gemm_f16<false>,
                         cudaFuncAttributeMaxDynamicSharedMemorySize, GSMEM);
    cudaFuncSetAttribute(gemm_f16<true>,
                         cudaFuncAttributeMaxDynamicSharedMemorySize, GSMEM);

    float *qk, *v, *p, *f;
    __half *xh, *aoh, *hh, *wqk, *wv, *wp, *wf;
    cudaGetSymbolAddress((void**)&qk,  g_qk);
    cudaGetSymbolAddress((void**)&v,   g_v);
    cudaGetSymbolAddress((void**)&p,   g_p);
    cudaGetSymbolAddress((void**)&f,   g_f);
    cudaGetSymbolAddress((void**)&xh,  g_xh);
    cudaGetSymbolAddress((void**)&aoh, g_aoh);
    cudaGetSymbolAddress((void**)&hh,  g_hh);
    cudaGetSymbolAddress((void**)&wqk, g_wqk);
    cudaGetSymbolAddress((void**)&wv,  g_wv);
    cudaGetSymbolAddress((void**)&wp,  g_wp);
    cudaGetSymbolAddress((void**)&wf,  g_wf);

    const dim3 blk(128);
    const int NX = M_TOK * K_E;        // 33.5M
    const int NW1 = N_QK * K_E;        // 2M
    const int NW2 = K_E * K_E;         // 1M

    // 0: fp32 -> fp16 conversions (x + 4 weight matrices)
    cvt_f2h<<<NX  / 2048, 256>>>(x,      xh,  NX);
    cvt_f2h<<<NW1 / 2048, 256>>>(qk_w,   wqk, NW1);
    cvt_f2h<<<NW2 / 2048, 256>>>(v_w,    wv,  NW2);
    cvt_f2h<<<NW2 / 2048, 256>>>(proj_w, wp,  NW2);
    cvt_f2h<<<NW2 / 2048, 256>>>(ff_w,   wf,  NW2);

    // 1-2: QKV projections
    gemm_f16<false><<<dim3(N_QK / 128, M_TOK / 128), blk, GSMEM>>>(
        xh, wqk, qk_b, qk, M_TOK, N_QK, K_E);
    gemm_f16<false><<<dim3(K_E / 128, M_TOK / 128), blk, GSMEM>>>(
        xh, wv, v_b, v, M_TOK, K_E, K_E);

    // 3: per-token head attention (fp16 out)
    attn_kernel<<<M_TOK, 128>>>(qk, v, aoh);

    // 4: output projection
    gemm_f16<false><<<dim3(K_E / 128, M_TOK / 128), blk, GSMEM>>>(
        aoh, wp, proj_b, p, M_TOK, K_E, K_E);

    // 5: h = LN(p + x)  (fp16 out)
    ln_kernel<true><<<M_TOK / 8, 256>>>(p, x, ln_g, ln_b, hh);

    // 6: f = gelu(h @ ff_w^T + ff_b)
    gemm_f16<true><<<dim3(K_E / 128, M_TOK / 128), blk, GSMEM>>>(
        hh, wf, ff_b, f, M_TOK, K_E, K_E);

    // 7: out = LN(f + x)  (fp32 out)
    ln_kernel<false><<<M_TOK / 8, 256>>>(f, x, ln_g, ln_b, out);
}

// round 14
// speedup vs baseline: 1.9307x; 1.0334x over previous
#include <cuda_runtime.h>
#include <cuda_fp16.h>
#include <cstdint>

// ---------------------------------------------------------------------------
// Problem dims (fixed by the reference): E=1024, H=16, DQ=DV=64, B=8, S=4096
// ---------------------------------------------------------------------------
#define M_TOK 32768      // B*S tokens
#define K_E   1024       // embedding dim
#define N_QK  2048       // H*(DQ+DQ)

// ---------------------------------------------------------------------------
// Scratch (static __device__ — no runtime allocation allowed). All
// intermediates are fp16: every consumer either rounds to fp16 anyway (GEMMs)
// or renormalizes (LN), so fp32 staging was pure wasted DRAM bandwidth.
// ---------------------------------------------------------------------------
__device__ __half g_qkh[(size_t)M_TOK * N_QK];   // QKV gemm out / attn in
__device__ __half g_vh [(size_t)M_TOK * K_E];
__device__ __half g_aoh[(size_t)M_TOK * K_E];    // attn out / proj in
__device__ __half g_ph [(size_t)M_TOK * K_E];    // proj out / LN1 in
__device__ __half g_hh [(size_t)M_TOK * K_E];    // LN1 out / ff in
__device__ __half g_fh [(size_t)M_TOK * K_E];    // ff out / LN2 in
__device__ __half g_xh [(size_t)M_TOK * K_E];    // x in fp16 (gemm A + residual)
__device__ __half g_wqk[(size_t)N_QK * K_E];     // fp16 weights
__device__ __half g_wv [(size_t)K_E * K_E];
__device__ __half g_wp [(size_t)K_E * K_E];
__device__ __half g_wf [(size_t)K_E * K_E];

// ---------------------------------------------------------------------------
// PTX helpers (plain sm_103 target: no 'a'-features; legacy mma.sync path)
// ---------------------------------------------------------------------------
__device__ __forceinline__ uint32_t smem_u32(const void* p) {
    return (uint32_t)__cvta_generic_to_shared(p);
}
__device__ __forceinline__ void cp_async16(uint32_t dst, const void* src) {
    asm volatile("cp.async.cg.shared.global [%0], [%1], 16;\n" :: "r"(dst), "l"(src));
}
__device__ __forceinline__ void cp_commit() {
    asm volatile("cp.async.commit_group;\n");
}
template <int N>
__device__ __forceinline__ void cp_wait() {
    asm volatile("cp.async.wait_group %0;\n" :: "n"(N));
}
__device__ __forceinline__ void ldsm_x4(uint32_t* r, uint32_t a) {
    asm volatile("ldmatrix.sync.aligned.m8n8.x4.shared.b16 {%0,%1,%2,%3}, [%4];\n"
                 : "=r"(r[0]), "=r"(r[1]), "=r"(r[2]), "=r"(r[3]) : "r"(a));
}
__device__ __forceinline__ void mma_f16(float* d, const uint32_t* a, const uint32_t* b) {
    asm volatile("mma.sync.aligned.m16n8k16.row.col.f32.f16.f16.f32 "
                 "{%0,%1,%2,%3}, {%4,%5,%6,%7}, {%8,%9}, {%0,%1,%2,%3};\n"
                 : "+f"(d[0]), "+f"(d[1]), "+f"(d[2]), "+f"(d[3])
                 : "r"(a[0]), "r"(a[1]), "r"(a[2]), "r"(a[3]),
                   "r"(b[0]), "r"(b[1]));
}

// ---------------------------------------------------------------------------
// fp32 -> fp16 conversion (vectorized, 8 elems/thread)
// ---------------------------------------------------------------------------
__global__ void __launch_bounds__(256) cvt_f2h(
    const float* __restrict__ in, __half* __restrict__ out, int n)
{
    int i = (blockIdx.x * 256 + threadIdx.x) << 3;
    if (i >= n) return;
    float4 a = *(const float4*)(in + i);
    float4 b = *(const float4*)(in + i + 4);
    __half2 h0 = __floats2half2_rn(a.x, a.y);
    __half2 h1 = __floats2half2_rn(a.z, a.w);
    __half2 h2 = __floats2half2_rn(b.x, b.y);
    __half2 h3 = __floats2half2_rn(b.z, b.w);
    uint4 u;
    u.x = *(uint32_t*)&h0; u.y = *(uint32_t*)&h1;
    u.z = *(uint32_t*)&h2; u.w = *(uint32_t*)&h3;
    *(uint4*)(out + i) = u;
}

// ---------------------------------------------------------------------------
// fp16 GEMM: C[M,N] = A[M,K]h @ W[N,K]h^T + bias[N]  (opt exact GELU)
// BM=128, BN=128, BK=64 halves. 128 threads = 4 warps (2x2), warp tile 64x64.
// 2 CTAs/SM, 3-stage cp.async pipeline (96 KB), one __syncthreads per k-tile,
// fragment double buffering with cross-tile ks=0 preload.
// HALF_OUT stores __half (all intermediates); else fp32.
// ---------------------------------------------------------------------------
#define STAGE_F 8192                 // uint32 per stage: 4096 A + 4096 B
#define GSMEM   (3 * STAGE_F * 4)    // 98304 bytes

__device__ __forceinline__ void gemm_load_tiles(
    float* as, const __half* Ag, const __half* Wg, int K, int lr, int lc)
{
    float* bs = as + 4096;
#pragma unroll
    for (int i = 0; i < 8; ++i) {            // A: 128 rows, 16 rows/pass
        int row = lr + (i << 4);
        int sw  = ((lc ^ (row & 7)) << 2);
        cp_async16(smem_u32(as + row * 32 + sw), Ag + (size_t)row * K + (lc << 3));
    }
#pragma unroll
    for (int i = 0; i < 8; ++i) {            // B: 128 rows
        int row = lr + (i << 4);
        int sw  = ((lc ^ (row & 7)) << 2);
        cp_async16(smem_u32(bs + row * 32 + sw), Wg + (size_t)row * K + (lc << 3));
    }
}

__device__ __forceinline__ void load_frags(
    uint32_t af[4][4], uint32_t bf[8][2], const float* as, int ks,
    int wm, int wn, int ro, int co)
{
    const float* bs = as + 4096;
    const int cg = (ks << 1) + co;
#pragma unroll
    for (int mi = 0; mi < 4; ++mi) {
        int row = wm + (mi << 4) + ro;
        ldsm_x4(af[mi], smem_u32(as + row * 32 + ((cg ^ (row & 7)) << 2)));
    }
#pragma unroll
    for (int jj = 0; jj < 4; ++jj) {
        int n = wn + (jj << 4) + ro;
        uint32_t t[4];
        ldsm_x4(t, smem_u32(bs + n * 32 + ((cg ^ (n & 7)) << 2)));
        bf[jj * 2    ][0] = t[0]; bf[jj * 2    ][1] = t[2];   // n0-7
        bf[jj * 2 + 1][0] = t[1]; bf[jj * 2 + 1][1] = t[3];   // n8-15
    }
}

__device__ __forceinline__ void mma_all(
    float acc[4][8][4], uint32_t af[4][4], uint32_t bf[8][2])
{
#pragma unroll
    for (int mi = 0; mi < 4; ++mi)
#pragma unroll
        for (int nj = 0; nj < 8; ++nj)
            mma_f16(acc[mi][nj], af[mi], bf[nj]);
}

template <bool GELU, bool HALF_OUT>
__global__ void __launch_bounds__(128, 2) gemm_f16(
    const __half* __restrict__ A, const __half* __restrict__ W,
    const float* __restrict__ bias, void* __restrict__ C,
    int M, int N, int K)
{
    extern __shared__ float smem[];   // 3 stages x 8192 uint32 = 96 KB

    const int tid  = threadIdx.x;
    const int lane = tid & 31;
    const int warp = tid >> 5;
    const int bm = blockIdx.y << 7;
    const int bn = blockIdx.x << 7;
    const int wm = (warp & 1) << 6;
    const int wn = (warp >> 1) << 6;

    const int lr = tid >> 3;
    const int lc = tid & 7;
    const int KT = K >> 6;

    const int ro = (((lane >> 3) & 1) << 3) + (lane & 7);
    const int co = lane >> 4;

    float acc[4][8][4];
#pragma unroll
    for (int i = 0; i < 4; ++i)
#pragma unroll
        for (int j = 0; j < 8; ++j) {
            acc[i][j][0] = 0.f; acc[i][j][1] = 0.f;
            acc[i][j][2] = 0.f; acc[i][j][3] = 0.f;
        }

    const __half* Abase = A + (size_t)bm * K;
    const __half* Wbase = W + (size_t)bn * K;

#pragma unroll
    for (int p = 0; p < 2; ++p) {
        gemm_load_tiles(smem + p * STAGE_F, Abase + (p << 6), Wbase + (p << 6),
                        K, lr, lc);
        cp_commit();
    }
    cp_wait<1>();
    __syncthreads();

    uint32_t af[2][4][4], bf[2][8][2];
    load_frags(af[0], bf[0], smem, 0, wm, wn, ro, co);
    int cur = 0;

    int s_cur = 0;
    for (int kt = 0; kt < KT; ++kt) {
        const float* as = smem + s_cur * STAGE_F;
        const int s_nxt = (s_cur + 1 == 3) ? 0 : s_cur + 1;
        const int s_fre = s_cur ? s_cur - 1 : 2;

#pragma unroll
        for (int ks = 0; ks < 3; ++ks) {
            load_frags(af[cur ^ 1], bf[cur ^ 1], as, ks + 1, wm, wn, ro, co);
            mma_all(acc, af[cur], bf[cur]);
            cur ^= 1;
        }

        if (kt + 1 < KT) {
            if (kt + 2 < KT)
                gemm_load_tiles(smem + s_fre * STAGE_F,
                                Abase + ((size_t)(kt + 2) << 6),
                                Wbase + ((size_t)(kt + 2) << 6),
                                K, lr, lc);
            cp_commit();
            cp_wait<1>();
            __syncthreads();
            load_frags(af[cur ^ 1], bf[cur ^ 1],
                       smem + s_nxt * STAGE_F, 0, wm, wn, ro, co);
        }
        mma_all(acc, af[cur], bf[cur]);    // ks = 3
        cur ^= 1;
        s_cur = s_nxt;
    }

    // epilogue: bias (+gelu), stores fp16 or fp32
    const int g  = lane >> 2;
    const int tg = lane & 3;
#pragma unroll
    for (int mi = 0; mi < 4; ++mi) {
        int r0 = bm + wm + (mi << 4) + g;
#pragma unroll
        for (int nj = 0; nj < 8; ++nj) {
            int col = bn + wn + (nj << 3) + (tg << 1);
            float b0 = bias[col], b1 = bias[col + 1];
            float v0 = acc[mi][nj][0] + b0;
            float v1 = acc[mi][nj][1] + b1;
            float v2 = acc[mi][nj][2] + b0;
            float v3 = acc[mi][nj][3] + b1;
            if (GELU) {
                v0 *= normcdff(v0);
                v1 *= normcdff(v1);
                v2 *= normcdff(v2);
                v3 *= normcdff(v3);
            }
            if (HALF_OUT) {
                __half* Ch = (__half*)C;
                *(__half2*)(Ch + (size_t)r0 * N + col)       = __floats2half2_rn(v0, v1);
                *(__half2*)(Ch + (size_t)(r0 + 8) * N + col) = __floats2half2_rn(v2, v3);
            } else {
                float* Cf = (float*)C;
                *(float2*)(Cf + (size_t)r0 * N + col)       = make_float2(v0, v1);
                *(float2*)(Cf + (size_t)(r0 + 8) * N + col) = make_float2(v2, v3);
            }
        }
    }
}

// ---------------------------------------------------------------------------
// Per-token head attention. fp16 in (qk, v) -> fp32 smem compute -> fp16 out.
// Conflict-free padded layout from R12 retained.
// ---------------------------------------------------------------------------
#define KSTR 68    // padded k-row stride (floats)
#define ASTR 17    // padded attn-row stride (floats)

__device__ __forceinline__ void unpack8(const uint4 u, float* dst) {
    float2 f0 = __half22float2(*(__half2*)&u.x);
    float2 f1 = __half22float2(*(__half2*)&u.y);
    float2 f2 = __half22float2(*(__half2*)&u.z);
    float2 f3 = __half22float2(*(__half2*)&u.w);
    dst[0] = f0.x; dst[1] = f0.y; dst[2] = f1.x; dst[3] = f1.y;
    dst[4] = f2.x; dst[5] = f2.y; dst[6] = f3.x; dst[7] = f3.y;
}

__global__ void __launch_bounds__(128) attn_kernel(
    const __half* __restrict__ QK, const __half* __restrict__ V,
    __half* __restrict__ O)
{
    const int t   = blockIdx.x;
    const int tid = threadIdx.x;
    __shared__ float qs[1024], ks2[15 * KSTR + 64 + 4], vs[1024], at[16 * ASTR];

    const uint4* qk8 = (const uint4*)(QK + (size_t)t * 2048);  // 256 x 8 halves
    const uint4* v8  = (const uint4*)(V  + (size_t)t * 1024);  // 128 x 8 halves

    {   // q: chunks 0..127 (one per thread)
        unpack8(qk8[tid], qs + tid * 8);
        // k: chunks 128..255 -> padded rows
        int kg = tid >> 3, col = (tid & 7) << 3;
        unpack8(qk8[128 + tid], ks2 + kg * KSTR + col);
        // v
        unpack8(v8[tid], vs + tid * 8);
    }
    __syncthreads();

#pragma unroll
    for (int sidx = tid; sidx < 256; sidx += 128) {
        int h = sidx >> 4, gg = sidx & 15;
        const float4* qp = (const float4*)(qs  + h  * 64);
        const float4* kp = (const float4*)(ks2 + gg * KSTR);
        float a = 0.f;
#pragma unroll
        for (int d = 0; d < 16; ++d) {
            float4 x = qp[d], y = kp[d];
            a += x.x * y.x + x.y * y.y + x.z * y.z + x.w * y.w;
        }
        at[h * ASTR + gg] = a * 0.125f;
    }
    __syncthreads();

    if (tid < 16) {
        float m = -1e30f;
#pragma unroll
        for (int gg = 0; gg < 16; ++gg) m = fmaxf(m, at[tid * ASTR + gg]);
        float s = 0.f;
#pragma unroll
        for (int gg = 0; gg < 16; ++gg) {
            float e = expf(at[tid * ASTR + gg] - m);
            at[tid * ASTR + gg] = e;
            s += e;
        }
        float inv = 1.f / s;
#pragma unroll
        for (int gg = 0; gg < 16; ++gg) at[tid * ASTR + gg] *= inv;
    }
    __syncthreads();

    __half2* out = (__half2*)(O + (size_t)t * 1024);
#pragma unroll
    for (int oo = tid; oo < 512; oo += 128) {
        int o = oo << 1;
        int h = o >> 6, d = o & 63;
        float a0 = 0.f, a1 = 0.f;
#pragma unroll
        for (int gg = 0; gg < 16; ++gg) {
            float w = at[h * ASTR + gg];
            a0 += w * vs[gg * 64 + d];
            a1 += w * vs[gg * 64 + d + 1];
        }
        out[oo] = __floats2half2_rn(a0, a1);
    }
}

// ---------------------------------------------------------------------------
// LayerNorm of (P + X) over last dim 1024; P and X fp16, fp32 internals.
// One warp per token; row lives in registers.
// HALF_OUT writes fp16 (feeds FF GEMM); else fp32 (final output).
// ---------------------------------------------------------------------------
template <bool HALF_OUT>
__global__ void __launch_bounds__(256) ln_kernel(
    const __half* __restrict__ P, const __half* __restrict__ X,
    const float* __restrict__ gw, const float* __restrict__ bw,
    void* __restrict__ Optr)
{
    const int t    = blockIdx.x * 8 + (threadIdx.x >> 5);
    const int lane = threadIdx.x & 31;
    const uint2* p4 = (const uint2*)(P + (size_t)t * 1024);  // 4 halves / uint2
    const uint2* x4 = (const uint2*)(X + (size_t)t * 1024);

    float4 v[8];
    float s = 0.f;
#pragma unroll
    for (int j = 0; j < 8; ++j) {
        int i = lane + (j << 5);
        uint2 ua = p4[i], uc = x4[i];
        float2 a0 = __half22float2(*(__half2*)&ua.x);
        float2 a1 = __half22float2(*(__half2*)&ua.y);
        float2 c0 = __half22float2(*(__half2*)&uc.x);
        float2 c1 = __half22float2(*(__half2*)&uc.y);
        v[j].x = a0.x + c0.x; v[j].y = a0.y + c0.y;
        v[j].z = a1.x + c1.x; v[j].w = a1.y + c1.y;
        s += v[j].x + v[j].y + v[j].z + v[j].w;
    }
#pragma unroll
    for (int o = 16; o > 0; o >>= 1) s += __shfl_xor_sync(0xffffffffu, s, o);
    const float mu = s * (1.0f / 1024.0f);

    float q = 0.f;
#pragma unroll
    for (int j = 0; j < 8; ++j) {
        float dx;
        dx = v[j].x - mu; q += dx * dx;
        dx = v[j].y - mu; q += dx * dx;
        dx = v[j].z - mu; q += dx * dx;
        dx = v[j].w - mu; q += dx * dx;
    }
#pragma unroll
    for (int o = 16; o > 0; o >>= 1) q += __shfl_xor_sync(0xffffffffu, q, o);
    const float r = rsqrtf(q * (1.0f / 1024.0f) + 1e-5f);

    const float4* g4 = (const float4*)gw;
    const float4* b4 = (const float4*)bw;
#pragma unroll
    for (int j = 0; j < 8; ++j) {
        int i = lane + (j << 5);
        float4 gg = g4[i], bb = b4[i], ov;
        ov.x = (v[j].x - mu) * r * gg.x + bb.x;
        ov.y = (v[j].y - mu) * r * gg.y + bb.y;
        ov.z = (v[j].z - mu) * r * gg.z + bb.z;
        ov.w = (v[j].w - mu) * r * gg.w + bb.w;
        if (HALF_OUT) {
            __half2 h0 = __floats2half2_rn(ov.x, ov.y);
            __half2 h1 = __floats2half2_rn(ov.z, ov.w);
            uint2 u;
            u.x = *(uint32_t*)&h0; u.y = *(uint32_t*)&h1;
            *(uint2*)((__half*)Optr + (size_t)t * 1024 + (i << 2)) = u;
        } else {
            *(float4*)((float*)Optr + (size_t)t * 1024 + (i << 2)) = ov;
        }
    }
}

// ---------------------------------------------------------------------------
// Launch
// ---------------------------------------------------------------------------
extern "C" void kernel_launch(void* const* d_in, const int* in_sizes, int n_in,
                              void* d_out, int out_size)
{
    const float* x      = (const float*)d_in[0];
    const float* qk_w   = (const float*)d_in[1];
    const float* qk_b   = (const float*)d_in[2];
    const float* v_w    = (const float*)d_in[3];
    const float* v_b    = (const float*)d_in[4];
    const float* proj_w = (const float*)d_in[5];
    const float* proj_b = (const float*)d_in[6];
    const float* ff_w   = (const float*)d_in[7];
    const float* ff_b   = (const float*)d_in[8];
    const float* ln_g   = (const float*)d_in[9];
    const float* ln_b   = (const float*)d_in[10];
    float* out = (float*)d_out;
    (void)in_sizes; (void)n_in; (void)out_size;

    cudaFuncSetAttribute((const void*)gemm_f16<false, true>,
                         cudaFuncAttributeMaxDynamicSharedMemorySize, GSMEM);
    cudaFuncSetAttribute((const void*)gemm_f16<true, true>,
                         cudaFuncAttributeMaxDynamicSharedMemorySize, GSMEM);

    __half *qkh, *vh, *aoh, *ph, *hh, *fh, *xh, *wqk, *wv, *wp, *wf;
    cudaGetSymbolAddress((void**)&qkh, g_qkh);
    cudaGetSymbolAddress((void**)&vh,  g_vh);
    cudaGetSymbolAddress((void**)&aoh, g_aoh);
    cudaGetSymbolAddress((void**)&ph,  g_ph);
    cudaGetSymbolAddress((void**)&hh,  g_hh);
    cudaGetSymbolAddress((void**)&fh,  g_fh);
    cudaGetSymbolAddress((void**)&xh,  g_xh);
    cudaGetSymbolAddress((void**)&wqk, g_wqk);
    cudaGetSymbolAddress((void**)&wv,  g_wv);
    cudaGetSymbolAddress((void**)&wp,  g_wp);
    cudaGetSymbolAddress((void**)&wf,  g_wf);

    const dim3 blk(128);
    const int NX  = M_TOK * K_E;       // 33.5M
    const int NW1 = N_QK * K_E;        // 2M
    const int NW2 = K_E * K_E;         // 1M

    // 0: fp32 -> fp16 conversions (x + 4 weight matrices)
    cvt_f2h<<<NX  / 2048, 256>>>(x,      xh,  NX);
    cvt_f2h<<<NW1 / 2048, 256>>>(qk_w,   wqk, NW1);
    cvt_f2h<<<NW2 / 2048, 256>>>(v_w,    wv,  NW2);
    cvt_f2h<<<NW2 / 2048, 256>>>(proj_w, wp,  NW2);
    cvt_f2h<<<NW2 / 2048, 256>>>(ff_w,   wf,  NW2);

    // 1-2: QKV projections (fp16 out)
    gemm_f16<false, true><<<dim3(N_QK / 128, M_TOK / 128), blk, GSMEM>>>(
        xh, wqk, qk_b, qkh, M_TOK, N_QK, K_E);
    gemm_f16<false, true><<<dim3(K_E / 128, M_TOK / 128), blk, GSMEM>>>(
        xh, wv, v_b, vh, M_TOK, K_E, K_E);

    // 3: per-token head attention (fp16 in/out)
    attn_kernel<<<M_TOK, 128>>>(qkh, vh, aoh);

    // 4: output projection (fp16 out)
    gemm_f16<false, true><<<dim3(K_E / 128, M_TOK / 128), blk, GSMEM>>>(
        aoh, wp, proj_b, ph, M_TOK, K_E, K_E);

    // 5: h = LN(p + x)  (fp16 out)
    ln_kernel<true><<<M_TOK / 8, 256>>>(ph, xh, ln_g, ln_b, hh);

    // 6: f = gelu(h @ ff_w^T + ff_b)  (fp16 out)
    gemm_f16<true, true><<<dim3(K_E / 128, M_TOK / 128), blk, GSMEM>>>(
        hh, wf, ff_b, fh, M_TOK, K_E, K_E);

    // 7: out = LN(f + x)  (fp32 out)
    ln_kernel<false><<<M_TOK / 8, 256>>>(fh, xh, ln_g, ln_b, out);
}